// round 11
// baseline (speedup 1.0000x reference)
#include <cuda_runtime.h>
#include <cuda_fp16.h>
#include <cstdint>

#define CB 2
#define CC 128
#define CCK 64
#define CH 256
#define CW 512
#define CH2 128
#define CW2 256
#define HWF (CH*CW)
#define HW2 (CH2*CW2)
#define NPIXF (CB*HWF)
#define NPIX2 (CB*HW2)
#define GRD 148

#define CTY 4
#define CTX 16
#define HX 18
#define NH 108
#define KP 66
#define VP 133
#define AP 13

typedef unsigned long long ull;
typedef unsigned int u32;
typedef unsigned short u16;

__device__ __forceinline__ ull fma2(ull a, ull b, ull c) {
    ull d; asm("fma.rn.f32x2 %0, %1, %2, %3;" : "=l"(d) : "l"(a), "l"(b), "l"(c)); return d;
}
__device__ __forceinline__ ull pk2(float x) {
    ull r; asm("mov.b64 %0, {%1, %1};" : "=l"(r) : "f"(x)); return r;
}
__device__ __forceinline__ ull pk2p(float x, float y) {
    ull r; asm("mov.b64 %0, {%1, %2};" : "=l"(r) : "f"(x), "f"(y)); return r;
}
__device__ __forceinline__ float2 upk(ull v) {
    float2 o; asm("mov.b64 {%0, %1}, %2;" : "=f"(o.x), "=f"(o.y) : "l"(v)); return o;
}
__device__ __forceinline__ ull ld2(const float* p) { return *reinterpret_cast<const ull*>(p); }

__device__ __forceinline__ void ldsm4(u32* r, const __half* p) {
    u32 sa = (u32)__cvta_generic_to_shared(p);
    asm volatile("ldmatrix.sync.aligned.m8n8.x4.shared.b16 {%0,%1,%2,%3}, [%4];"
        : "=r"(r[0]), "=r"(r[1]), "=r"(r[2]), "=r"(r[3]) : "r"(sa));
}
__device__ __forceinline__ void mma16816(float* c, const u32* a, u32 b0, u32 b1) {
    asm volatile("mma.sync.aligned.m16n8k16.row.col.f32.f16.f16.f32 "
        "{%0,%1,%2,%3}, {%4,%5,%6,%7}, {%8,%9}, {%0,%1,%2,%3};"
        : "+f"(c[0]), "+f"(c[1]), "+f"(c[2]), "+f"(c[3])
        : "r"(a[0]), "r"(a[1]), "r"(a[2]), "r"(a[3]), "r"(b0), "r"(b1));
}
__device__ __forceinline__ u32 cvt2(float hiF, float loF) {
    u32 r; asm("cvt.rn.f16x2.f32 %0, %1, %2;" : "=r"(r) : "f"(hiF), "f"(loF)); return r;
}

// ---- bulk-copy (UBLKCP) staging ----
__device__ __forceinline__ void bulk_g2s(u32 dst_smem, const void* src, u32 bytes, u32 mbar) {
    asm volatile("cp.async.bulk.shared::cluster.global.mbarrier::complete_tx::bytes "
        "[%0], [%1], %2, [%3];"
        :: "r"(dst_smem), "l"(src), "r"(bytes), "r"(mbar) : "memory");
}
__device__ __forceinline__ void mbar_init(u32 mbar, u32 cnt) {
    asm volatile("mbarrier.init.shared.b64 [%0], %1;" :: "r"(mbar), "r"(cnt) : "memory");
}
__device__ __forceinline__ void mbar_expect(u32 mbar, u32 bytes) {
    asm volatile("mbarrier.arrive.expect_tx.shared.b64 _, [%0], %1;"
        :: "r"(mbar), "r"(bytes) : "memory");
}
__device__ __forceinline__ void mbar_wait(u32 mbar, u32 parity) {
    asm volatile(
        "{\n\t"
        ".reg .pred P1;\n\t"
        "WAIT_%=:\n\t"
        "mbarrier.try_wait.parity.acquire.cta.shared::cta.b64 P1, [%0], %1;\n\t"
        "@!P1 bra WAIT_%=;\n\t"
        "}"
        :: "r"(mbar), "r"(parity) : "memory");
}

__device__ __half g_k16[(size_t)NPIX2*CCK];
__device__ __half g_v16[(size_t)NPIX2*CC];
__device__ __half g_q16[(size_t)NPIXF*CCK];
__device__ __half g_x16[(size_t)NPIXF*CC];   // NCHW
__device__ float  g_Wc[CC*CC];
__device__ float  g_beff[CC];

__global__ void k_fuse(const float* __restrict__ Wout, const float* __restrict__ Wvi,
                       const float* __restrict__ bvi, const float* __restrict__ bout) {
    int o = blockIdx.x, i = threadIdx.x;
    float acc = 0.f;
    for (int m = 0; m < CC; m++) acc += Wout[o*CC + m] * Wvi[m*CC + i];
    g_Wc[o*CC + i] = acc;
    if (i == 0) {
        float b = bout[o];
        for (int m = 0; m < CC; m++) b += Wout[o*CC + m] * bvi[m];
        g_beff[o] = b;
    }
}

// fp16 2-product GEMM mainloop: W split (hi+lo fp16), X fp32 smem -> fp16 frag.
template<int MF, int NF, int KT, int XP, int KPW>
__device__ __forceinline__ void gemm_ms(const __half* __restrict__ Wh,
                                        const __half* __restrict__ Wl,
                                        const float* __restrict__ Xs,
                                        float C[MF][NF][4], int m0, int n0, int lane) {
    const int lrow = (lane & 7) + ((lane >> 3) & 1) * 8;
    const int lk8  = ((lane >> 4) & 1) * 8;
    const int bn   = n0 + (lane >> 2);
    const int bk   = 2 * (lane & 3);
    for (int ks = 0; ks < KT/16; ks++) {
        u32 ah[MF][4], al[MF][4];
        #pragma unroll
        for (int i = 0; i < MF; i++) {
            int off = (m0 + i*16 + lrow)*KPW + ks*16 + lk8;
            ldsm4(ah[i], Wh + off);
            ldsm4(al[i], Wl + off);
        }
        u32 bh[NF][2];
        #pragma unroll
        for (int j = 0; j < NF; j++) {
            const float* xp = Xs + (ks*16 + bk)*XP + bn + j*8;
            float x0 = xp[0], x1 = xp[XP], x2 = xp[8*XP], x3 = xp[9*XP];
            bh[j][0] = cvt2(x1, x0);
            bh[j][1] = cvt2(x3, x2);
        }
        #pragma unroll
        for (int i = 0; i < MF; i++)
            #pragma unroll
            for (int j = 0; j < NF; j++) mma16816(C[i][j], ah[i], bh[j][0], bh[j][1]);
        #pragma unroll
        for (int i = 0; i < MF; i++)
            #pragma unroll
            for (int j = 0; j < NF; j++) mma16816(C[i][j], al[i], bh[j][0], bh[j][1]);
    }
}

// Variant: X already fp16 in smem.
template<int MF, int NF, int KT, int XP, int KPW>
__device__ __forceinline__ void gemm_ms16(const __half* __restrict__ Wh,
                                          const __half* __restrict__ Wl,
                                          const __half* __restrict__ Xs,
                                          float C[MF][NF][4], int m0, int n0, int lane) {
    const int lrow = (lane & 7) + ((lane >> 3) & 1) * 8;
    const int lk8  = ((lane >> 4) & 1) * 8;
    const int bn   = n0 + (lane >> 2);
    const int bk   = 2 * (lane & 3);
    for (int ks = 0; ks < KT/16; ks++) {
        u32 ah[MF][4], al[MF][4];
        #pragma unroll
        for (int i = 0; i < MF; i++) {
            int off = (m0 + i*16 + lrow)*KPW + ks*16 + lk8;
            ldsm4(ah[i], Wh + off);
            ldsm4(al[i], Wl + off);
        }
        u32 bh[NF][2];
        #pragma unroll
        for (int j = 0; j < NF; j++) {
            const __half* xp = Xs + (ks*16 + bk)*XP + bn + j*8;
            u16 x0 = __half_as_ushort(xp[0]),    x1 = __half_as_ushort(xp[XP]);
            u16 x2 = __half_as_ushort(xp[8*XP]), x3 = __half_as_ushort(xp[9*XP]);
            bh[j][0] = ((u32)x1 << 16) | x0;
            bh[j][1] = ((u32)x3 << 16) | x2;
        }
        #pragma unroll
        for (int i = 0; i < MF; i++)
            #pragma unroll
            for (int j = 0; j < NF; j++) mma16816(C[i][j], ah[i], bh[j][0], bh[j][1]);
        #pragma unroll
        for (int i = 0; i < MF; i++)
            #pragma unroll
            for (int j = 0; j < NF; j++) mma16816(C[i][j], al[i], bh[j][0], bh[j][1]);
    }
}

__device__ __forceinline__ void w_split(float w, __half* Wh, __half* Wl, int off) {
    __half h = __float2half_rn(w);
    Wh[off] = h;
    Wl[off] = __float2half_rn(w - __half2float(h));
}

// K1: coarse k,v. M=192, K=128, BN=32. Bulk-copy staging. fp16 outputs.
#define KV_W_BYTES (192*136*2*2)
#define KV_STG     (128*36*4)
#define KV_SS_OFF  (KV_W_BYTES + 2*KV_STG)
#define KV_MB_OFF  (KV_SS_OFF + 32*196*4)
#define KV_SMEM    (KV_MB_OFF + 16)
__global__ void __launch_bounds__(256) k_kv(const float* __restrict__ hp,
        const float* __restrict__ Wk, const float* __restrict__ bk,
        const float* __restrict__ Wvp, const float* __restrict__ bvp) {
    extern __shared__ char smraw[];
    __half* Wh = (__half*)smraw;
    __half* Wl = Wh + 192*136;
    float* Xs = (float*)(smraw + KV_W_BYTES);
    float* Ss = (float*)(smraw + KV_SS_OFF);
    int t = threadIdx.x;
    u32 base_u32 = (u32)__cvta_generic_to_shared(smraw);
    u32 mb_u32 = base_u32 + KV_MB_OFF;

    for (int idx = t; idx < 192*128; idx += 256) {
        int m = idx >> 7, k = idx & 127;
        float w = (m < 64) ? Wk[m*128 + k] : Wvp[(m - 64)*128 + k];
        w_split(w, Wh, Wl, m*136 + k);
    }
    if (t == 0) { mbar_init(mb_u32, 1); mbar_init(mb_u32 + 8, 1); }
    __syncthreads();

    const int NT = NPIX2/32;
    int lane = t & 31, warp = t >> 5;
    auto issue_tile = [&](int buf, int tile) {   // warp 0 only
        int p0 = tile*32, bb = p0 >> 15, s0 = p0 & (HW2 - 1);
        const float* hb = hp + (size_t)bb*128*HW2 + s0;
        u32 mb = mb_u32 + buf*8;
        if (lane == 0) mbar_expect(mb, 128*128);
        __syncwarp();
        u32 xbase = base_u32 + KV_W_BYTES + buf*KV_STG;
        #pragma unroll
        for (int rr = 0; rr < 4; rr++) {
            int r = lane + 32*rr;
            bulk_g2s(xbase + r*144, hb + (size_t)r*HW2, 128, mb);
        }
    };
    int wm = warp >> 1, wn = warp & 1;
    int m0 = wm*48, n0 = wn*16;
    int r0 = m0 + (lane >> 2);

    int tile = blockIdx.x, par = 0;
    int ph[2] = {0, 0};
    if (warp == 0 && tile < NT) issue_tile(0, tile);
    for (; tile < NT; tile += GRD) {
        int nxt = tile + GRD;
        if (warp == 0 && nxt < NT) issue_tile(par ^ 1, nxt);
        mbar_wait(mb_u32 + par*8, ph[par]); ph[par] ^= 1;

        float C[3][2][4];
        #pragma unroll
        for (int i = 0; i < 3; i++) {
            int ra = r0 + i*16, rb = ra + 8;
            float b0 = (ra < 64) ? bk[ra] : bvp[ra - 64];
            float b1 = (rb < 64) ? bk[rb] : bvp[rb - 64];
            #pragma unroll
            for (int j = 0; j < 2; j++) {
                C[i][j][0] = C[i][j][1] = b0;
                C[i][j][2] = C[i][j][3] = b1;
            }
        }
        gemm_ms<3,2,128,36,136>(Wh, Wl, Xs + par*128*36, C, m0, n0, lane);
        __syncthreads();
        #pragma unroll
        for (int i = 0; i < 3; i++)
            #pragma unroll
            for (int j = 0; j < 2; j++) {
                int pc = n0 + j*8 + 2*(lane & 3);
                int rr = m0 + i*16 + (lane >> 2);
                Ss[pc*196 + rr]           = C[i][j][0];
                Ss[(pc + 1)*196 + rr]     = C[i][j][1];
                Ss[pc*196 + rr + 8]       = C[i][j][2];
                Ss[(pc + 1)*196 + rr + 8] = C[i][j][3];
            }
        __syncthreads();
        int p0 = tile*32;
        #pragma unroll
        for (int c = 0; c < 2; c++) {
            int idx = t + 256*c;
            int p = idx >> 4, f4 = idx & 15;
            float4 v = *(const float4*)(Ss + p*196 + f4*4);
            u32 h0 = cvt2(v.y, v.x), h1 = cvt2(v.w, v.z);
            *(uint2*)(g_k16 + (size_t)(p0 + p)*64 + f4*4) = make_uint2(h0, h1);
        }
        #pragma unroll
        for (int c = 0; c < 4; c++) {
            int idx = t + 256*c;
            int p = idx >> 5, f5 = idx & 31;
            float4 v = *(const float4*)(Ss + p*196 + 64 + f5*4);
            u32 h0 = cvt2(v.y, v.x), h1 = cvt2(v.w, v.z);
            *(uint2*)(g_v16 + (size_t)(p0 + p)*128 + f5*4) = make_uint2(h0, h1);
        }
        __syncthreads();
        par ^= 1;
    }
}

// K2: q. M=64, K=128, BN=128. Bulk-copy staging. Outputs g_q16.
#define Q_W_BYTES (64*136*2*2)
#define Q_STG     (128*132*4)
#define Q_SS_OFF  (Q_W_BYTES + 2*Q_STG)
#define Q_MB_OFF  (Q_SS_OFF + 128*68*4)
#define Q_SMEM    (Q_MB_OFF + 16)
__global__ void __launch_bounds__(256) k_q(const float* __restrict__ hi,
        const float* __restrict__ Wq, const float* __restrict__ bq) {
    extern __shared__ char smraw[];
    __half* Wh = (__half*)smraw;
    __half* Wl = Wh + 64*136;
    float* Xs = (float*)(smraw + Q_W_BYTES);
    float* Ss = (float*)(smraw + Q_SS_OFF);
    int t = threadIdx.x;
    u32 base_u32 = (u32)__cvta_generic_to_shared(smraw);
    u32 mb_u32 = base_u32 + Q_MB_OFF;

    for (int idx = t; idx < 64*128; idx += 256) {
        int m = idx >> 7, k = idx & 127;
        w_split(Wq[idx], Wh, Wl, m*136 + k);
    }
    if (t == 0) { mbar_init(mb_u32, 1); mbar_init(mb_u32 + 8, 1); }
    __syncthreads();

    const int NT = NPIXF/128;
    int lane = t & 31, warp = t >> 5;
    auto issue_tile = [&](int buf, int tile) {
        int p0 = tile*128, bb = p0 >> 17, s0 = p0 & (HWF - 1);
        const float* hb = hi + (size_t)bb*128*HWF + s0;
        u32 mb = mb_u32 + buf*8;
        if (lane == 0) mbar_expect(mb, 128*512);
        __syncwarp();
        u32 xbase = base_u32 + Q_W_BYTES + buf*Q_STG;
        #pragma unroll
        for (int rr = 0; rr < 4; rr++) {
            int r = lane + 32*rr;
            bulk_g2s(xbase + r*528, hb + (size_t)r*HWF, 512, mb);
        }
    };
    int wm = warp >> 2, wn = warp & 3;
    int m0 = wm*32, n0 = wn*32;
    int r0 = m0 + (lane >> 2);

    int tile = blockIdx.x, par = 0;
    int ph[2] = {0, 0};
    if (warp == 0 && tile < NT) issue_tile(0, tile);
    for (; tile < NT; tile += GRD) {
        int nxt = tile + GRD;
        if (warp == 0 && nxt < NT) issue_tile(par ^ 1, nxt);
        mbar_wait(mb_u32 + par*8, ph[par]); ph[par] ^= 1;

        float C[2][4][4];
        #pragma unroll
        for (int i = 0; i < 2; i++) {
            float b0 = bq[r0 + i*16], b1 = bq[r0 + i*16 + 8];
            #pragma unroll
            for (int j = 0; j < 4; j++) {
                C[i][j][0] = C[i][j][1] = b0;
                C[i][j][2] = C[i][j][3] = b1;
            }
        }
        gemm_ms<2,4,128,132,136>(Wh, Wl, Xs + par*128*132, C, m0, n0, lane);
        __syncthreads();
        #pragma unroll
        for (int i = 0; i < 2; i++)
            #pragma unroll
            for (int j = 0; j < 4; j++) {
                int pc = n0 + j*8 + 2*(lane & 3);
                int rr = m0 + i*16 + (lane >> 2);
                Ss[pc*68 + rr]           = C[i][j][0];
                Ss[(pc + 1)*68 + rr]     = C[i][j][1];
                Ss[pc*68 + rr + 8]       = C[i][j][2];
                Ss[(pc + 1)*68 + rr + 8] = C[i][j][3];
            }
        __syncthreads();
        int p0 = tile*128;
        #pragma unroll
        for (int c = 0; c < 8; c++) {
            int idx = t + 256*c;
            int p = idx >> 4, f4 = idx & 15;
            float4 v = *(const float4*)(Ss + p*68 + f4*4);
            u32 h0 = cvt2(v.y, v.x), h1 = cvt2(v.w, v.z);
            *(uint2*)(g_q16 + (size_t)(p0 + p)*64 + f4*4) = make_uint2(h0, h1);
        }
        __syncthreads();
        par ^= 1;
    }
}

// K3: attention (round-10 proven). fp16 k/v/q in, fp16 x out.
#define ATTN_SMEM ((NH*KP + NH*VP + 256*AP)*4)
__global__ void __launch_bounds__(256) k_attn() {
    extern __shared__ float sm[];
    float* ks = sm;
    float* vs = ks + NH*KP;
    float* as = vs + NH*VP;
    int t = threadIdx.x;
    int b = blockIdx.z;
    int cy0 = blockIdx.y * CTY, cx0 = blockIdx.x * CTX;
    int fy0 = cy0*2, fx0 = cx0*2;

    for (int idx = t; idx < NH*8; idx += 256) {
        int pix = idx >> 3, c8 = idx & 7;
        int hy = pix / HX, hx = pix % HX;
        int gy = cy0 + hy - 1, gx = cx0 + hx - 1;
        float* d = ks + pix*KP + c8*8;
        if ((unsigned)gy < CH2 && (unsigned)gx < CW2) {
            uint4 v = *(const uint4*)(g_k16 + ((size_t)(b*HW2 + gy*CW2 + gx))*CCK + c8*8);
            float2 f0 = __half22float2(*reinterpret_cast<__half2*>(&v.x));
            float2 f1 = __half22float2(*reinterpret_cast<__half2*>(&v.y));
            float2 f2 = __half22float2(*reinterpret_cast<__half2*>(&v.z));
            float2 f3 = __half22float2(*reinterpret_cast<__half2*>(&v.w));
            d[0] = f0.x; d[1] = f0.y; d[2] = f1.x; d[3] = f1.y;
            d[4] = f2.x; d[5] = f2.y; d[6] = f3.x; d[7] = f3.y;
        } else {
            #pragma unroll
            for (int i = 0; i < 8; i++) d[i] = 0.f;
        }
    }
    for (int idx = t; idx < NH*16; idx += 256) {
        int pix = idx >> 4, c8 = idx & 15;
        int hy = pix / HX, hx = pix % HX;
        int gy = cy0 + hy - 1, gx = cx0 + hx - 1;
        float* d = vs + pix*VP + c8*8;
        if ((unsigned)gy < CH2 && (unsigned)gx < CW2) {
            uint4 v = *(const uint4*)(g_v16 + ((size_t)(b*HW2 + gy*CW2 + gx))*CC + c8*8);
            float2 f0 = __half22float2(*reinterpret_cast<__half2*>(&v.x));
            float2 f1 = __half22float2(*reinterpret_cast<__half2*>(&v.y));
            float2 f2 = __half22float2(*reinterpret_cast<__half2*>(&v.z));
            float2 f3 = __half22float2(*reinterpret_cast<__half2*>(&v.w));
            d[0] = f0.x; d[1] = f0.y; d[2] = f1.x; d[3] = f1.y;
            d[4] = f2.x; d[5] = f2.y; d[6] = f3.x; d[7] = f3.y;
        } else {
            #pragma unroll
            for (int i = 0; i < 8; i++) d[i] = 0.f;
        }
    }
    __syncthreads();

    {   // Phase A
        int p = t;
        int fy = p >> 5, fx = p & 31;
        int cy = fy >> 1, cx = fx >> 1;
        const uint4* gq = reinterpret_cast<const uint4*>(
            g_q16 + ((size_t)((b*CH + fy0 + fy)*CW + fx0 + fx))*CCK);
        const float* kb = ks + (cy*HX + cx)*KP;
        ull sc2[9];
        #pragma unroll
        for (int j = 0; j < 9; j++) sc2[j] = 0ull;
        #pragma unroll 2
        for (int cc = 0; cc < 8; cc++) {
            uint4 qv = gq[cc];
            float2 f0 = __half22float2(*reinterpret_cast<__half2*>(&qv.x));
            float2 f1 = __half22float2(*reinterpret_cast<__half2*>(&qv.y));
            float2 f2 = __half22float2(*reinterpret_cast<__half2*>(&qv.z));
            float2 f3 = __half22float2(*reinterpret_cast<__half2*>(&qv.w));
            ull q0 = pk2p(f0.x, f0.y), q1 = pk2p(f1.x, f1.y);
            ull q2 = pk2p(f2.x, f2.y), q3 = pk2p(f3.x, f3.y);
            int c = cc*8;
            #pragma unroll
            for (int dy = 0; dy < 3; dy++)
                #pragma unroll
                for (int dx = 0; dx < 3; dx++) {
                    int j = dy*3 + dx;
                    const float* kp = kb + (dy*HX + dx)*KP + c;
                    sc2[j] = fma2(q0, ld2(kp),     sc2[j]);
                    sc2[j] = fma2(q1, ld2(kp + 2), sc2[j]);
                    sc2[j] = fma2(q2, ld2(kp + 4), sc2[j]);
                    sc2[j] = fma2(q3, ld2(kp + 6), sc2[j]);
                }
        }
        float sc[9];
        #pragma unroll
        for (int j = 0; j < 9; j++) { float2 v = upk(sc2[j]); sc[j] = v.x + v.y; }
        float m = sc[0];
        #pragma unroll
        for (int j = 1; j < 9; j++) m = fmaxf(m, sc[j]);
        float s = 0.f;
        #pragma unroll
        for (int j = 0; j < 9; j++) { sc[j] = __expf(sc[j] - m); s += sc[j]; }
        float inv = 1.f / s;
        #pragma unroll
        for (int j = 0; j < 9; j++) as[p*AP + j] = sc[j]*inv;
    }
    __syncthreads();

    {   // Phase B
        int cell = t & 63, cg = t >> 6;
        int cyl = cell >> 4, cxl = cell & 15;
        ull a01[9], a23[9];
        int p00 = (2*cyl)*32 + 2*cxl;
        int p10 = p00 + 32;
        #pragma unroll
        for (int j = 0; j < 9; j++) {
            a01[j] = pk2p(as[p00*AP + j], as[(p00 + 1)*AP + j]);
            a23[j] = pk2p(as[p10*AP + j], as[(p10 + 1)*AP + j]);
        }
        const float* vb = vs + (cyl*HX + cxl)*VP + cg*32;
        size_t obase = ((size_t)(b*CC + cg*32))*HWF
                     + (size_t)(fy0 + 2*cyl)*CW + fx0 + 2*cxl;
        for (int cc = 0; cc < 32; cc++) {
            ull o01 = 0ull, o23 = 0ull;
            #pragma unroll
            for (int dy = 0; dy < 3; dy++)
                #pragma unroll
                for (int dx = 0; dx < 3; dx++) {
                    int j = dy*3 + dx;
                    ull vv = pk2(vb[(dy*HX + dx)*VP + cc]);
                    o01 = fma2(a01[j], vv, o01);
                    o23 = fma2(a23[j], vv, o23);
                }
            float2 r01 = upk(o01), r23 = upk(o23);
            size_t oa = obase + (size_t)cc*HWF;
            *reinterpret_cast<u32*>(g_x16 + oa)      = cvt2(r01.y, r01.x);
            *reinterpret_cast<u32*>(g_x16 + oa + CW) = cvt2(r23.y, r23.x);
        }
    }
}

// K4: out. M=128, K=256 as two K=128 passes. BN=32. Bulk-copy staging.
#define XP16 40
#define O_W_BYTES  (128*264*2*2)
#define O_STG32    (128*36*4)
#define O_X16_OFF  (O_W_BYTES + 2*O_STG32)
#define O_STG16    (128*XP16*2)
#define O_MB_OFF   (O_X16_OFF + 2*O_STG16)
#define O_SMEM     (O_MB_OFF + 16)
__global__ void __launch_bounds__(256) k_out(const float* __restrict__ hi,
        const float* __restrict__ Wout, float* __restrict__ out) {
    extern __shared__ char smraw[];
    __half* Wh = (__half*)smraw;
    __half* Wl = Wh + 128*264;
    float* Xs32 = (float*)(smraw + O_W_BYTES);
    __half* Xs16 = (__half*)(smraw + O_X16_OFF);
    int t = threadIdx.x;
    u32 base_u32 = (u32)__cvta_generic_to_shared(smraw);
    u32 mb_u32 = base_u32 + O_MB_OFF;

    for (int idx = t; idx < 128*256; idx += 256) {
        int m = idx >> 8, k = idx & 255;
        float w = (k < 128) ? g_Wc[m*128 + k] : Wout[m*128 + (k - 128)];
        w_split(w, Wh, Wl, m*264 + k);
    }
    if (t == 0) { mbar_init(mb_u32, 1); mbar_init(mb_u32 + 8, 1); }
    __syncthreads();

    const int NT = NPIXF/32;
    int lane = t & 31, warp = t >> 5;
    auto issue_tile = [&](int buf, int tile) {
        int p0 = tile*32, bb = p0 >> 17, s0 = p0 & (HWF - 1);
        const float* hb = hi + (size_t)bb*128*HWF + s0;
        const __half* xb = g_x16 + (size_t)bb*128*HWF + s0;
        u32 mb = mb_u32 + buf*8;
        if (lane == 0) mbar_expect(mb, 128*128 + 128*64);
        __syncwarp();
        u32 x32 = base_u32 + O_W_BYTES + buf*O_STG32;
        u32 x16 = base_u32 + O_X16_OFF + buf*O_STG16;
        #pragma unroll
        for (int rr = 0; rr < 4; rr++) {
            int r = lane + 32*rr;
            bulk_g2s(x32 + r*144, hb + (size_t)r*HWF, 128, mb);
        }
        #pragma unroll
        for (int rr = 0; rr < 4; rr++) {
            int r = lane + 32*rr;
            bulk_g2s(x16 + r*80, xb + (size_t)r*HWF, 64, mb);
        }
    };
    int wm = warp >> 1, wn = warp & 1;
    int m0 = wm*32, n0 = wn*16;
    int r0 = m0 + (lane >> 2);

    int tile = blockIdx.x, par = 0;
    int ph[2] = {0, 0};
    if (warp == 0 && tile < NT) issue_tile(0, tile);
    for (; tile < NT; tile += GRD) {
        int nxt = tile + GRD;
        if (warp == 0 && nxt < NT) issue_tile(par ^ 1, nxt);
        mbar_wait(mb_u32 + par*8, ph[par]); ph[par] ^= 1;

        float C[2][2][4];
        #pragma unroll
        for (int i = 0; i < 2; i++) {
            float b0 = g_beff[r0 + i*16], b1 = g_beff[r0 + i*16 + 8];
            #pragma unroll
            for (int j = 0; j < 2; j++) {
                C[i][j][0] = C[i][j][1] = b0;
                C[i][j][2] = C[i][j][3] = b1;
            }
        }
        gemm_ms<2,2,128,36,264>(Wh, Wl, Xs32 + par*128*36, C, m0, n0, lane);
        gemm_ms16<2,2,128,XP16,264>(Wh + 128, Wl + 128, Xs16 + par*128*XP16, C, m0, n0, lane);

        int p0 = tile*32, bb = p0 >> 17, s0 = p0 & (HWF - 1);
        float* ob = out + (size_t)bb*128*HWF + s0;
        int cb = n0 + 2*(lane & 3);
        #pragma unroll
        for (int i = 0; i < 2; i++) {
            int r = r0 + i*16;
            #pragma unroll
            for (int j = 0; j < 2; j++) {
                int ccol = cb + j*8;
                *(float2*)(ob + (size_t)r*HWF + ccol)       = make_float2(C[i][j][0], C[i][j][1]);
                *(float2*)(ob + (size_t)(r + 8)*HWF + ccol) = make_float2(C[i][j][2], C[i][j][3]);
            }
        }
        __syncthreads();
        par ^= 1;
    }
}

extern "C" void kernel_launch(void* const* d_in, const int* in_sizes, int n_in,
                              void* d_out, int out_size) {
    const float* h_prev = (const float*)d_in[0];
    const float* h_init = (const float*)d_in[1];
    const float* Wq   = (const float*)d_in[2];
    const float* bq   = (const float*)d_in[3];
    const float* Wk   = (const float*)d_in[4];
    const float* bk   = (const float*)d_in[5];
    const float* Wvp  = (const float*)d_in[6];
    const float* bvp  = (const float*)d_in[7];
    const float* Wvi  = (const float*)d_in[8];
    const float* bvi  = (const float*)d_in[9];
    const float* Wout = (const float*)d_in[10];
    const float* bout = (const float*)d_in[11];
    float* out = (float*)d_out;

    cudaFuncSetAttribute(k_kv,   cudaFuncAttributeMaxDynamicSharedMemorySize, KV_SMEM);
    cudaFuncSetAttribute(k_q,    cudaFuncAttributeMaxDynamicSharedMemorySize, Q_SMEM);
    cudaFuncSetAttribute(k_attn, cudaFuncAttributeMaxDynamicSharedMemorySize, ATTN_SMEM);
    cudaFuncSetAttribute(k_out,  cudaFuncAttributeMaxDynamicSharedMemorySize, O_SMEM);

    k_fuse<<<CC, CC>>>(Wout, Wvi, bvi, bout);
    k_kv<<<GRD, 256, KV_SMEM>>>(h_prev, Wk, bk, Wvp, bvp);
    k_q<<<GRD, 256, Q_SMEM>>>(h_init, Wq, bq);
    dim3 ag(CW2/CTX, CH2/CTY, CB);
    k_attn<<<ag, 256, ATTN_SMEM>>>();
    k_out<<<GRD, 256, O_SMEM>>>(h_init, Wout, out);
}

// round 12
// speedup vs baseline: 2.2105x; 2.2105x over previous
#include <cuda_runtime.h>
#include <cuda_fp16.h>
#include <cstdint>

#define CB 2
#define CC 128
#define CCK 64
#define CH 256
#define CW 512
#define CH2 128
#define CW2 256
#define HWF (CH*CW)
#define HW2 (CH2*CW2)
#define NPIXF (CB*HWF)
#define NPIX2 (CB*HW2)
#define GRD 148

#define CTY 4
#define CTX 16
#define HX 18
#define NH 108
#define KP 66
#define VP 132
#define AP 13

typedef unsigned long long ull;
typedef unsigned int u32;
typedef unsigned short u16;

__device__ __forceinline__ ull fma2(ull a, ull b, ull c) {
    ull d; asm("fma.rn.f32x2 %0, %1, %2, %3;" : "=l"(d) : "l"(a), "l"(b), "l"(c)); return d;
}
__device__ __forceinline__ ull pk2(float x) {
    ull r; asm("mov.b64 %0, {%1, %1};" : "=l"(r) : "f"(x)); return r;
}
__device__ __forceinline__ ull pk2p(float x, float y) {
    ull r; asm("mov.b64 %0, {%1, %2};" : "=l"(r) : "f"(x), "f"(y)); return r;
}
__device__ __forceinline__ float2 upk(ull v) {
    float2 o; asm("mov.b64 {%0, %1}, %2;" : "=f"(o.x), "=f"(o.y) : "l"(v)); return o;
}
__device__ __forceinline__ ull ld2(const float* p) { return *reinterpret_cast<const ull*>(p); }

__device__ __forceinline__ void ldsm4(u32* r, const __half* p) {
    u32 sa = (u32)__cvta_generic_to_shared(p);
    asm volatile("ldmatrix.sync.aligned.m8n8.x4.shared.b16 {%0,%1,%2,%3}, [%4];"
        : "=r"(r[0]), "=r"(r[1]), "=r"(r[2]), "=r"(r[3]) : "r"(sa));
}
__device__ __forceinline__ void mma16816(float* c, const u32* a, u32 b0, u32 b1) {
    asm volatile("mma.sync.aligned.m16n8k16.row.col.f32.f16.f16.f32 "
        "{%0,%1,%2,%3}, {%4,%5,%6,%7}, {%8,%9}, {%0,%1,%2,%3};"
        : "+f"(c[0]), "+f"(c[1]), "+f"(c[2]), "+f"(c[3])
        : "r"(a[0]), "r"(a[1]), "r"(a[2]), "r"(a[3]), "r"(b0), "r"(b1));
}
__device__ __forceinline__ u32 cvt2(float hiF, float loF) {
    u32 r; asm("cvt.rn.f16x2.f32 %0, %1, %2;" : "=r"(r) : "f"(hiF), "f"(loF)); return r;
}
__device__ __forceinline__ void cpa16(void* dst, const void* src) {
    u32 d = (u32)__cvta_generic_to_shared(dst);
    asm volatile("cp.async.cg.shared.global [%0], [%1], 16;" :: "r"(d), "l"(src));
}
#define CPA_COMMIT() asm volatile("cp.async.commit_group;")
#define CPA_WAIT1()  asm volatile("cp.async.wait_group 1;")

__device__ __half g_k16[(size_t)NPIX2*CCK];
__device__ __half g_v16[(size_t)NPIX2*CC];
__device__ __half g_q16[(size_t)NPIXF*CCK];
__device__ __half g_h16[(size_t)NPIXF*CC];   // fp16 copy of h_init, NCHW
__device__ __half g_x16[(size_t)NPIXF*CC];   // NCHW
__device__ float  g_Wc[CC*CC];
__device__ float  g_beff[CC];

__global__ void k_fuse(const float* __restrict__ Wout, const float* __restrict__ Wvi,
                       const float* __restrict__ bvi, const float* __restrict__ bout) {
    int o = blockIdx.x, i = threadIdx.x;
    float acc = 0.f;
    for (int m = 0; m < CC; m++) acc += Wout[o*CC + m] * Wvi[m*CC + i];
    g_Wc[o*CC + i] = acc;
    if (i == 0) {
        float b = bout[o];
        for (int m = 0; m < CC; m++) b += Wout[o*CC + m] * bvi[m];
        g_beff[o] = b;
    }
}

// fp16 2-product GEMM mainloop: W split (hi+lo fp16), X fp32 smem -> fp16 frag.
template<int MF, int NF, int KT, int XP, int KPW>
__device__ __forceinline__ void gemm_ms(const __half* __restrict__ Wh,
                                        const __half* __restrict__ Wl,
                                        const float* __restrict__ Xs,
                                        float C[MF][NF][4], int m0, int n0, int lane) {
    const int lrow = (lane & 7) + ((lane >> 3) & 1) * 8;
    const int lk8  = ((lane >> 4) & 1) * 8;
    const int bn   = n0 + (lane >> 2);
    const int bk   = 2 * (lane & 3);
    for (int ks = 0; ks < KT/16; ks++) {
        u32 ah[MF][4], al[MF][4];
        #pragma unroll
        for (int i = 0; i < MF; i++) {
            int off = (m0 + i*16 + lrow)*KPW + ks*16 + lk8;
            ldsm4(ah[i], Wh + off);
            ldsm4(al[i], Wl + off);
        }
        u32 bh[NF][2];
        #pragma unroll
        for (int j = 0; j < NF; j++) {
            const float* xp = Xs + (ks*16 + bk)*XP + bn + j*8;
            float x0 = xp[0], x1 = xp[XP], x2 = xp[8*XP], x3 = xp[9*XP];
            bh[j][0] = cvt2(x1, x0);
            bh[j][1] = cvt2(x3, x2);
        }
        #pragma unroll
        for (int i = 0; i < MF; i++)
            #pragma unroll
            for (int j = 0; j < NF; j++) mma16816(C[i][j], ah[i], bh[j][0], bh[j][1]);
        #pragma unroll
        for (int i = 0; i < MF; i++)
            #pragma unroll
            for (int j = 0; j < NF; j++) mma16816(C[i][j], al[i], bh[j][0], bh[j][1]);
    }
}

// Variant: X already fp16 in smem.
template<int MF, int NF, int KT, int XP, int KPW>
__device__ __forceinline__ void gemm_ms16(const __half* __restrict__ Wh,
                                          const __half* __restrict__ Wl,
                                          const __half* __restrict__ Xs,
                                          float C[MF][NF][4], int m0, int n0, int lane) {
    const int lrow = (lane & 7) + ((lane >> 3) & 1) * 8;
    const int lk8  = ((lane >> 4) & 1) * 8;
    const int bn   = n0 + (lane >> 2);
    const int bk   = 2 * (lane & 3);
    for (int ks = 0; ks < KT/16; ks++) {
        u32 ah[MF][4], al[MF][4];
        #pragma unroll
        for (int i = 0; i < MF; i++) {
            int off = (m0 + i*16 + lrow)*KPW + ks*16 + lk8;
            ldsm4(ah[i], Wh + off);
            ldsm4(al[i], Wl + off);
        }
        u32 bh[NF][2];
        #pragma unroll
        for (int j = 0; j < NF; j++) {
            const __half* xp = Xs + (ks*16 + bk)*XP + bn + j*8;
            u16 x0 = __half_as_ushort(xp[0]),    x1 = __half_as_ushort(xp[XP]);
            u16 x2 = __half_as_ushort(xp[8*XP]), x3 = __half_as_ushort(xp[9*XP]);
            bh[j][0] = ((u32)x1 << 16) | x0;
            bh[j][1] = ((u32)x3 << 16) | x2;
        }
        #pragma unroll
        for (int i = 0; i < MF; i++)
            #pragma unroll
            for (int j = 0; j < NF; j++) mma16816(C[i][j], ah[i], bh[j][0], bh[j][1]);
        #pragma unroll
        for (int i = 0; i < MF; i++)
            #pragma unroll
            for (int j = 0; j < NF; j++) mma16816(C[i][j], al[i], bh[j][0], bh[j][1]);
    }
}

__device__ __forceinline__ void w_split(float w, __half* Wh, __half* Wl, int off) {
    __half h = __float2half_rn(w);
    Wh[off] = h;
    Wl[off] = __float2half_rn(w - __half2float(h));
}

// K1: coarse k,v. M=192, K=128, BN=32. cp.async staging. fp16 outputs.
#define KV_SMEM (192*136*2*2 + 2*128*36*4 + 32*196*4)
__global__ void __launch_bounds__(256) k_kv(const float* __restrict__ hp,
        const float* __restrict__ Wk, const float* __restrict__ bk,
        const float* __restrict__ Wvp, const float* __restrict__ bvp) {
    extern __shared__ char smraw[];
    __half* Wh = (__half*)smraw;
    __half* Wl = Wh + 192*136;
    float* Xs = (float*)(smraw + 192*136*2*2);
    float* Ss = Xs + 2*128*36;
    int t = threadIdx.x;

    for (int idx = t; idx < 192*128; idx += 256) {
        int m = idx >> 7, k = idx & 127;
        float w = (m < 64) ? Wk[m*128 + k] : Wvp[(m - 64)*128 + k];
        w_split(w, Wh, Wl, m*136 + k);
    }
    const int NT = NPIX2/32;
    auto load_tile = [&](int buf, int tile) {
        float* X = Xs + buf*128*36;
        int p0 = tile*32, bb = p0 >> 15, s0 = p0 & (HW2 - 1);
        const float* hb = hp + (size_t)bb*128*HW2 + s0;
        #pragma unroll
        for (int c8 = 0; c8 < 4; c8++) {
            int chunk = t + 256*c8;
            int r = chunk >> 3, q = chunk & 7;
            cpa16(X + r*36 + q*4, hb + (size_t)r*HW2 + q*4);
        }
    };
    int lane = t & 31, warp = t >> 5;
    int wm = warp >> 1, wn = warp & 1;
    int m0 = wm*48, n0 = wn*16;
    int r0 = m0 + (lane >> 2);

    int tile = blockIdx.x, par = 0;
    if (tile < NT) load_tile(0, tile);
    CPA_COMMIT();
    __syncthreads();
    for (; tile < NT; tile += GRD) {
        int nxt = tile + GRD;
        if (nxt < NT) load_tile(par ^ 1, nxt);
        CPA_COMMIT();
        CPA_WAIT1();
        __syncthreads();

        float C[3][2][4];
        #pragma unroll
        for (int i = 0; i < 3; i++) {
            int ra = r0 + i*16, rb = ra + 8;
            float b0 = (ra < 64) ? bk[ra] : bvp[ra - 64];
            float b1 = (rb < 64) ? bk[rb] : bvp[rb - 64];
            #pragma unroll
            for (int j = 0; j < 2; j++) {
                C[i][j][0] = C[i][j][1] = b0;
                C[i][j][2] = C[i][j][3] = b1;
            }
        }
        gemm_ms<3,2,128,36,136>(Wh, Wl, Xs + par*128*36, C, m0, n0, lane);
        __syncthreads();
        #pragma unroll
        for (int i = 0; i < 3; i++)
            #pragma unroll
            for (int j = 0; j < 2; j++) {
                int pc = n0 + j*8 + 2*(lane & 3);
                int rr = m0 + i*16 + (lane >> 2);
                Ss[pc*196 + rr]           = C[i][j][0];
                Ss[(pc + 1)*196 + rr]     = C[i][j][1];
                Ss[pc*196 + rr + 8]       = C[i][j][2];
                Ss[(pc + 1)*196 + rr + 8] = C[i][j][3];
            }
        __syncthreads();
        int p0 = tile*32;
        #pragma unroll
        for (int c = 0; c < 2; c++) {
            int idx = t + 256*c;
            int p = idx >> 4, f4 = idx & 15;
            float4 v = *(const float4*)(Ss + p*196 + f4*4);
            u32 h0 = cvt2(v.y, v.x), h1 = cvt2(v.w, v.z);
            *(uint2*)(g_k16 + (size_t)(p0 + p)*64 + f4*4) = make_uint2(h0, h1);
        }
        #pragma unroll
        for (int c = 0; c < 4; c++) {
            int idx = t + 256*c;
            int p = idx >> 5, f5 = idx & 31;
            float4 v = *(const float4*)(Ss + p*196 + 64 + f5*4);
            u32 h0 = cvt2(v.y, v.x), h1 = cvt2(v.w, v.z);
            *(uint2*)(g_v16 + (size_t)(p0 + p)*128 + f5*4) = make_uint2(h0, h1);
        }
        __syncthreads();
        par ^= 1;
    }
}

// K2: q. M=64, K=128, BN=128. cp.async staging. Outputs g_q16 + g_h16.
#define Q_SMEM (64*136*2*2 + 2*128*132*4 + 128*68*4)
__global__ void __launch_bounds__(256) k_q(const float* __restrict__ hi,
        const float* __restrict__ Wq, const float* __restrict__ bq) {
    extern __shared__ char smraw[];
    __half* Wh = (__half*)smraw;
    __half* Wl = Wh + 64*136;
    float* Xs = (float*)(smraw + 64*136*2*2);
    float* Ss = Xs + 2*128*132;
    int t = threadIdx.x;

    for (int idx = t; idx < 64*128; idx += 256) {
        int m = idx >> 7, k = idx & 127;
        w_split(Wq[idx], Wh, Wl, m*136 + k);
    }
    const int NT = NPIXF/128;
    auto load_tile = [&](int buf, int tile) {
        float* X = Xs + buf*128*132;
        int p0 = tile*128, bb = p0 >> 17, s0 = p0 & (HWF - 1);
        const float* hb = hi + (size_t)bb*128*HWF + s0;
        #pragma unroll
        for (int c8 = 0; c8 < 16; c8++) {
            int chunk = t + 256*c8;
            int r = chunk >> 5, q = chunk & 31;
            cpa16(X + r*132 + q*4, hb + (size_t)r*HWF + q*4);
        }
    };
    int lane = t & 31, warp = t >> 5;
    int wm = warp >> 2, wn = warp & 3;
    int m0 = wm*32, n0 = wn*32;
    int r0 = m0 + (lane >> 2);

    int tile = blockIdx.x, par = 0;
    if (tile < NT) load_tile(0, tile);
    CPA_COMMIT();
    __syncthreads();
    for (; tile < NT; tile += GRD) {
        int nxt = tile + GRD;
        if (nxt < NT) load_tile(par ^ 1, nxt);
        CPA_COMMIT();
        CPA_WAIT1();
        __syncthreads();

        float C[2][4][4];
        #pragma unroll
        for (int i = 0; i < 2; i++) {
            float b0 = bq[r0 + i*16], b1 = bq[r0 + i*16 + 8];
            #pragma unroll
            for (int j = 0; j < 4; j++) {
                C[i][j][0] = C[i][j][1] = b0;
                C[i][j][2] = C[i][j][3] = b1;
            }
        }
        gemm_ms<2,4,128,132,136>(Wh, Wl, Xs + par*128*132, C, m0, n0, lane);
        __syncthreads();
        #pragma unroll
        for (int i = 0; i < 2; i++)
            #pragma unroll
            for (int j = 0; j < 4; j++) {
                int pc = n0 + j*8 + 2*(lane & 3);
                int rr = m0 + i*16 + (lane >> 2);
                Ss[pc*68 + rr]           = C[i][j][0];
                Ss[(pc + 1)*68 + rr]     = C[i][j][1];
                Ss[pc*68 + rr + 8]       = C[i][j][2];
                Ss[(pc + 1)*68 + rr + 8] = C[i][j][3];
            }
        __syncthreads();
        int p0 = tile*128, bb = p0 >> 17, s0 = p0 & (HWF - 1);
        #pragma unroll
        for (int c = 0; c < 8; c++) {
            int idx = t + 256*c;
            int p = idx >> 4, f4 = idx & 15;
            float4 v = *(const float4*)(Ss + p*68 + f4*4);
            u32 h0 = cvt2(v.y, v.x), h1 = cvt2(v.w, v.z);
            *(uint2*)(g_q16 + (size_t)(p0 + p)*64 + f4*4) = make_uint2(h0, h1);
        }
        // byproduct: h16 (NCHW) from the fp32 staging tile
        {
            const float* X = Xs + par*128*132;
            #pragma unroll
            for (int c = 0; c < 8; c++) {
                int idx = t + 256*c;
                int r = idx >> 4, q8 = idx & 15;
                const float* xr = X + r*132 + q8*8;
                u32 h0 = cvt2(xr[1], xr[0]);
                u32 h1 = cvt2(xr[3], xr[2]);
                u32 h2 = cvt2(xr[5], xr[4]);
                u32 h3 = cvt2(xr[7], xr[6]);
                *(uint4*)(g_h16 + ((size_t)(bb*128 + r))*HWF + s0 + q8*8) =
                    make_uint4(h0, h1, h2, h3);
            }
        }
        __syncthreads();
        par ^= 1;
    }
}

// K3: attention. fp16 k/v/q in, fp16 x out. Phase B float4-vectorized.
#define ATTN_SMEM ((NH*KP + NH*VP + 256*AP)*4)
__global__ void __launch_bounds__(256) k_attn() {
    extern __shared__ float sm[];
    float* ks = sm;
    float* vs = ks + NH*KP;
    float* as = vs + NH*VP;
    int t = threadIdx.x;
    int b = blockIdx.z;
    int cy0 = blockIdx.y * CTY, cx0 = blockIdx.x * CTX;
    int fy0 = cy0*2, fx0 = cx0*2;

    for (int idx = t; idx < NH*8; idx += 256) {
        int pix = idx >> 3, c8 = idx & 7;
        int hy = pix / HX, hx = pix % HX;
        int gy = cy0 + hy - 1, gx = cx0 + hx - 1;
        float* d = ks + pix*KP + c8*8;
        if ((unsigned)gy < CH2 && (unsigned)gx < CW2) {
            uint4 v = *(const uint4*)(g_k16 + ((size_t)(b*HW2 + gy*CW2 + gx))*CCK + c8*8);
            float2 f0 = __half22float2(*reinterpret_cast<__half2*>(&v.x));
            float2 f1 = __half22float2(*reinterpret_cast<__half2*>(&v.y));
            float2 f2 = __half22float2(*reinterpret_cast<__half2*>(&v.z));
            float2 f3 = __half22float2(*reinterpret_cast<__half2*>(&v.w));
            d[0] = f0.x; d[1] = f0.y; d[2] = f1.x; d[3] = f1.y;
            d[4] = f2.x; d[5] = f2.y; d[6] = f3.x; d[7] = f3.y;
        } else {
            #pragma unroll
            for (int i = 0; i < 8; i++) d[i] = 0.f;
        }
    }
    for (int idx = t; idx < NH*16; idx += 256) {
        int pix = idx >> 4, c8 = idx & 15;
        int hy = pix / HX, hx = pix % HX;
        int gy = cy0 + hy - 1, gx = cx0 + hx - 1;
        float* d = vs + pix*VP + c8*8;
        if ((unsigned)gy < CH2 && (unsigned)gx < CW2) {
            uint4 v = *(const uint4*)(g_v16 + ((size_t)(b*HW2 + gy*CW2 + gx))*CC + c8*8);
            float2 f0 = __half22float2(*reinterpret_cast<__half2*>(&v.x));
            float2 f1 = __half22float2(*reinterpret_cast<__half2*>(&v.y));
            float2 f2 = __half22float2(*reinterpret_cast<__half2*>(&v.z));
            float2 f3 = __half22float2(*reinterpret_cast<__half2*>(&v.w));
            d[0] = f0.x; d[1] = f0.y; d[2] = f1.x; d[3] = f1.y;
            d[4] = f2.x; d[5] = f2.y; d[6] = f3.x; d[7] = f3.y;
        } else {
            #pragma unroll
            for (int i = 0; i < 8; i++) d[i] = 0.f;
        }
    }
    __syncthreads();

    {   // Phase A
        int p = t;
        int fy = p >> 5, fx = p & 31;
        int cy = fy >> 1, cx = fx >> 1;
        const uint4* gq = reinterpret_cast<const uint4*>(
            g_q16 + ((size_t)((b*CH + fy0 + fy)*CW + fx0 + fx))*CCK);
        const float* kb = ks + (cy*HX + cx)*KP;
        ull sc2[9];
        #pragma unroll
        for (int j = 0; j < 9; j++) sc2[j] = 0ull;
        #pragma unroll 2
        for (int cc = 0; cc < 8; cc++) {
            uint4 qv = gq[cc];
            float2 f0 = __half22float2(*reinterpret_cast<__half2*>(&qv.x));
            float2 f1 = __half22float2(*reinterpret_cast<__half2*>(&qv.y));
            float2 f2 = __half22float2(*reinterpret_cast<__half2*>(&qv.z));
            float2 f3 = __half22float2(*reinterpret_cast<__half2*>(&qv.w));
            ull q0 = pk2p(f0.x, f0.y), q1 = pk2p(f1.x, f1.y);
            ull q2 = pk2p(f2.x, f2.y), q3 = pk2p(f3.x, f3.y);
            int c = cc*8;
            #pragma unroll
            for (int dy = 0; dy < 3; dy++)
                #pragma unroll
                for (int dx = 0; dx < 3; dx++) {
                    int j = dy*3 + dx;
                    const float* kp = kb + (dy*HX + dx)*KP + c;
                    sc2[j] = fma2(q0, ld2(kp),     sc2[j]);
                    sc2[j] = fma2(q1, ld2(kp + 2), sc2[j]);
                    sc2[j] = fma2(q2, ld2(kp + 4), sc2[j]);
                    sc2[j] = fma2(q3, ld2(kp + 6), sc2[j]);
                }
        }
        float sc[9];
        #pragma unroll
        for (int j = 0; j < 9; j++) { float2 v = upk(sc2[j]); sc[j] = v.x + v.y; }
        float m = sc[0];
        #pragma unroll
        for (int j = 1; j < 9; j++) m = fmaxf(m, sc[j]);
        float s = 0.f;
        #pragma unroll
        for (int j = 0; j < 9; j++) { sc[j] = __expf(sc[j] - m); s += sc[j]; }
        float inv = 1.f / s;
        #pragma unroll
        for (int j = 0; j < 9; j++) as[p*AP + j] = sc[j]*inv;
    }
    __syncthreads();

    {   // Phase B: float4 v loads, 4 channels per iteration
        int cell = t & 63, cg = t >> 6;
        int cyl = cell >> 4, cxl = cell & 15;
        ull a01[9], a23[9];
        int p00 = (2*cyl)*32 + 2*cxl;
        int p10 = p00 + 32;
        #pragma unroll
        for (int j = 0; j < 9; j++) {
            a01[j] = pk2p(as[p00*AP + j], as[(p00 + 1)*AP + j]);
            a23[j] = pk2p(as[p10*AP + j], as[(p10 + 1)*AP + j]);
        }
        const float* vb = vs + (cyl*HX + cxl)*VP + cg*32;
        size_t obase = ((size_t)(b*CC + cg*32))*HWF
                     + (size_t)(fy0 + 2*cyl)*CW + fx0 + 2*cxl;
        #pragma unroll 2
        for (int c4 = 0; c4 < 8; c4++) {
            ull o01[4] = {0ull, 0ull, 0ull, 0ull};
            ull o23[4] = {0ull, 0ull, 0ull, 0ull};
            #pragma unroll
            for (int dy = 0; dy < 3; dy++)
                #pragma unroll
                for (int dx = 0; dx < 3; dx++) {
                    int j = dy*3 + dx;
                    float4 vv = *(const float4*)(vb + (dy*HX + dx)*VP + c4*4);
                    o01[0] = fma2(a01[j], pk2(vv.x), o01[0]);
                    o01[1] = fma2(a01[j], pk2(vv.y), o01[1]);
                    o01[2] = fma2(a01[j], pk2(vv.z), o01[2]);
                    o01[3] = fma2(a01[j], pk2(vv.w), o01[3]);
                    o23[0] = fma2(a23[j], pk2(vv.x), o23[0]);
                    o23[1] = fma2(a23[j], pk2(vv.y), o23[1]);
                    o23[2] = fma2(a23[j], pk2(vv.z), o23[2]);
                    o23[3] = fma2(a23[j], pk2(vv.w), o23[3]);
                }
            #pragma unroll
            for (int e = 0; e < 4; e++) {
                float2 r01 = upk(o01[e]), r23 = upk(o23[e]);
                size_t oa = obase + (size_t)(c4*4 + e)*HWF;
                *reinterpret_cast<u32*>(g_x16 + oa)      = cvt2(r01.y, r01.x);
                *reinterpret_cast<u32*>(g_x16 + oa + CW) = cvt2(r23.y, r23.x);
            }
        }
    }
}

// K4: out. M=128, two K=128 fp16 passes (h16, x16). BN=32. cp.async staging.
#define XP16 40
#define O_SMEM (128*264*2*2 + 4*128*XP16*2)
__global__ void __launch_bounds__(256) k_out(const float* __restrict__ hi,
        const float* __restrict__ Wout, float* __restrict__ out) {
    extern __shared__ char smraw[];
    __half* Wh = (__half*)smraw;
    __half* Wl = Wh + 128*264;
    __half* Xh = (__half*)(smraw + 128*264*2*2);            // 2 x [128][40]
    __half* Xx = Xh + 2*128*XP16;                           // 2 x [128][40]
    int t = threadIdx.x;

    for (int idx = t; idx < 128*256; idx += 256) {
        int m = idx >> 8, k = idx & 255;
        float w = (k < 128) ? g_Wc[m*128 + k] : Wout[m*128 + (k - 128)];
        w_split(w, Wh, Wl, m*264 + k);
    }
    const int NT = NPIXF/32;
    auto load_tile = [&](int buf, int tile) {
        __half* XH = Xh + buf*128*XP16;
        __half* XX = Xx + buf*128*XP16;
        int p0 = tile*32, bb = p0 >> 17, s0 = p0 & (HWF - 1);
        const __half* hb = g_h16 + (size_t)bb*128*HWF + s0;
        const __half* xb = g_x16 + (size_t)bb*128*HWF + s0;
        #pragma unroll
        for (int c8 = 0; c8 < 2; c8++) {
            int chunk = t + 256*c8;
            int r = chunk >> 2, q = chunk & 3;
            cpa16(XH + r*XP16 + q*8, hb + (size_t)r*HWF + q*8);
        }
        #pragma unroll
        for (int c8 = 0; c8 < 2; c8++) {
            int chunk = t + 256*c8;
            int r = chunk >> 2, q = chunk & 3;
            cpa16(XX + r*XP16 + q*8, xb + (size_t)r*HWF + q*8);
        }
    };
    int lane = t & 31, warp = t >> 5;
    int wm = warp >> 1, wn = warp & 1;
    int m0 = wm*32, n0 = wn*16;
    int r0 = m0 + (lane >> 2);

    int tile = blockIdx.x, par = 0;
    if (tile < NT) load_tile(0, tile);
    CPA_COMMIT();
    __syncthreads();
    for (; tile < NT; tile += GRD) {
        int nxt = tile + GRD;
        if (nxt < NT) load_tile(par ^ 1, nxt);
        CPA_COMMIT();
        CPA_WAIT1();
        __syncthreads();

        float C[2][2][4];
        #pragma unroll
        for (int i = 0; i < 2; i++) {
            float b0 = g_beff[r0 + i*16], b1 = g_beff[r0 + i*16 + 8];
            #pragma unroll
            for (int j = 0; j < 2; j++) {
                C[i][j][0] = C[i][j][1] = b0;
                C[i][j][2] = C[i][j][3] = b1;
            }
        }
        gemm_ms16<2,2,128,XP16,264>(Wh, Wl, Xh + par*128*XP16, C, m0, n0, lane);
        gemm_ms16<2,2,128,XP16,264>(Wh + 128, Wl + 128, Xx + par*128*XP16, C, m0, n0, lane);

        int p0 = tile*32, bb = p0 >> 17, s0 = p0 & (HWF - 1);
        float* ob = out + (size_t)bb*128*HWF + s0;
        int cb = n0 + 2*(lane & 3);
        #pragma unroll
        for (int i = 0; i < 2; i++) {
            int r = r0 + i*16;
            #pragma unroll
            for (int j = 0; j < 2; j++) {
                int ccol = cb + j*8;
                *(float2*)(ob + (size_t)r*HWF + ccol)       = make_float2(C[i][j][0], C[i][j][1]);
                *(float2*)(ob + (size_t)(r + 8)*HWF + ccol) = make_float2(C[i][j][2], C[i][j][3]);
            }
        }
        __syncthreads();
        par ^= 1;
    }
}

extern "C" void kernel_launch(void* const* d_in, const int* in_sizes, int n_in,
                              void* d_out, int out_size) {
    const float* h_prev = (const float*)d_in[0];
    const float* h_init = (const float*)d_in[1];
    const float* Wq   = (const float*)d_in[2];
    const float* bq   = (const float*)d_in[3];
    const float* Wk   = (const float*)d_in[4];
    const float* bk   = (const float*)d_in[5];
    const float* Wvp  = (const float*)d_in[6];
    const float* bvp  = (const float*)d_in[7];
    const float* Wvi  = (const float*)d_in[8];
    const float* bvi  = (const float*)d_in[9];
    const float* Wout = (const float*)d_in[10];
    const float* bout = (const float*)d_in[11];
    float* out = (float*)d_out;

    cudaFuncSetAttribute(k_kv,   cudaFuncAttributeMaxDynamicSharedMemorySize, KV_SMEM);
    cudaFuncSetAttribute(k_q,    cudaFuncAttributeMaxDynamicSharedMemorySize, Q_SMEM);
    cudaFuncSetAttribute(k_attn, cudaFuncAttributeMaxDynamicSharedMemorySize, ATTN_SMEM);
    cudaFuncSetAttribute(k_out,  cudaFuncAttributeMaxDynamicSharedMemorySize, O_SMEM);

    k_fuse<<<CC, CC>>>(Wout, Wvi, bvi, bout);
    k_kv<<<GRD, 256, KV_SMEM>>>(h_prev, Wk, bk, Wvp, bvp);
    k_q<<<GRD, 256, Q_SMEM>>>(h_init, Wq, bq);
    dim3 ag(CW2/CTX, CH2/CTY, CB);
    k_attn<<<ag, 256, ATTN_SMEM>>>();
    k_out<<<GRD, 256, O_SMEM>>>(h_init, Wout, out);
}

// round 13
// speedup vs baseline: 2.2560x; 1.0206x over previous
#include <cuda_runtime.h>
#include <cuda_fp16.h>
#include <cstdint>

#define CB 2
#define CC 128
#define CCK 64
#define CH 256
#define CW 512
#define CH2 128
#define CW2 256
#define HWF (CH*CW)
#define HW2 (CH2*CW2)
#define NPIXF (CB*HWF)
#define NPIX2 (CB*HW2)
#define GRD 148

#define CTY 4
#define CTX 16
#define HX 18
#define NH 108
#define KP 66
#define VP 132
#define AP 13

typedef unsigned long long ull;
typedef unsigned int u32;
typedef unsigned short u16;

__device__ __forceinline__ ull fma2(ull a, ull b, ull c) {
    ull d; asm("fma.rn.f32x2 %0, %1, %2, %3;" : "=l"(d) : "l"(a), "l"(b), "l"(c)); return d;
}
__device__ __forceinline__ ull pk2(float x) {
    ull r; asm("mov.b64 %0, {%1, %1};" : "=l"(r) : "f"(x)); return r;
}
__device__ __forceinline__ ull pk2p(float x, float y) {
    ull r; asm("mov.b64 %0, {%1, %2};" : "=l"(r) : "f"(x), "f"(y)); return r;
}
__device__ __forceinline__ float2 upk(ull v) {
    float2 o; asm("mov.b64 {%0, %1}, %2;" : "=f"(o.x), "=f"(o.y) : "l"(v)); return o;
}
__device__ __forceinline__ ull ld2(const float* p) { return *reinterpret_cast<const ull*>(p); }

__device__ __forceinline__ void ldsm4(u32* r, const __half* p) {
    u32 sa = (u32)__cvta_generic_to_shared(p);
    asm volatile("ldmatrix.sync.aligned.m8n8.x4.shared.b16 {%0,%1,%2,%3}, [%4];"
        : "=r"(r[0]), "=r"(r[1]), "=r"(r[2]), "=r"(r[3]) : "r"(sa));
}
__device__ __forceinline__ void mma16816(float* c, const u32* a, u32 b0, u32 b1) {
    asm volatile("mma.sync.aligned.m16n8k16.row.col.f32.f16.f16.f32 "
        "{%0,%1,%2,%3}, {%4,%5,%6,%7}, {%8,%9}, {%0,%1,%2,%3};"
        : "+f"(c[0]), "+f"(c[1]), "+f"(c[2]), "+f"(c[3])
        : "r"(a[0]), "r"(a[1]), "r"(a[2]), "r"(a[3]), "r"(b0), "r"(b1));
}
__device__ __forceinline__ u32 cvt2(float hiF, float loF) {
    u32 r; asm("cvt.rn.f16x2.f32 %0, %1, %2;" : "=r"(r) : "f"(hiF), "f"(loF)); return r;
}
__device__ __forceinline__ void cpa16(void* dst, const void* src) {
    u32 d = (u32)__cvta_generic_to_shared(dst);
    asm volatile("cp.async.cg.shared.global [%0], [%1], 16;" :: "r"(d), "l"(src));
}
#define CPA_COMMIT() asm volatile("cp.async.commit_group;")
#define CPA_WAIT1()  asm volatile("cp.async.wait_group 1;")
#define CPA_WAIT2()  asm volatile("cp.async.wait_group 2;")

__device__ __half g_k16[(size_t)NPIX2*CCK];
__device__ __half g_v16[(size_t)NPIX2*CC];
__device__ __half g_q16[(size_t)NPIXF*CCK];
__device__ __half g_x16[(size_t)NPIXF*CC];   // NCHW
__device__ float  g_Wc[CC*CC];
__device__ float  g_beff[CC];

__global__ void k_fuse(const float* __restrict__ Wout, const float* __restrict__ Wvi,
                       const float* __restrict__ bvi, const float* __restrict__ bout) {
    int o = blockIdx.x, i = threadIdx.x;
    float acc = 0.f;
    for (int m = 0; m < CC; m++) acc += Wout[o*CC + m] * Wvi[m*CC + i];
    g_Wc[o*CC + i] = acc;
    if (i == 0) {
        float b = bout[o];
        for (int m = 0; m < CC; m++) b += Wout[o*CC + m] * bvi[m];
        g_beff[o] = b;
    }
}

// fp16 2-product GEMM mainloop: W split (hi+lo fp16), X fp32 smem -> fp16 frag.
template<int MF, int NF, int KT, int XP, int KPW>
__device__ __forceinline__ void gemm_ms(const __half* __restrict__ Wh,
                                        const __half* __restrict__ Wl,
                                        const float* __restrict__ Xs,
                                        float C[MF][NF][4], int m0, int n0, int lane) {
    const int lrow = (lane & 7) + ((lane >> 3) & 1) * 8;
    const int lk8  = ((lane >> 4) & 1) * 8;
    const int bn   = n0 + (lane >> 2);
    const int bk   = 2 * (lane & 3);
    for (int ks = 0; ks < KT/16; ks++) {
        u32 ah[MF][4], al[MF][4];
        #pragma unroll
        for (int i = 0; i < MF; i++) {
            int off = (m0 + i*16 + lrow)*KPW + ks*16 + lk8;
            ldsm4(ah[i], Wh + off);
            ldsm4(al[i], Wl + off);
        }
        u32 bh[NF][2];
        #pragma unroll
        for (int j = 0; j < NF; j++) {
            const float* xp = Xs + (ks*16 + bk)*XP + bn + j*8;
            float x0 = xp[0], x1 = xp[XP], x2 = xp[8*XP], x3 = xp[9*XP];
            bh[j][0] = cvt2(x1, x0);
            bh[j][1] = cvt2(x3, x2);
        }
        #pragma unroll
        for (int i = 0; i < MF; i++)
            #pragma unroll
            for (int j = 0; j < NF; j++) mma16816(C[i][j], ah[i], bh[j][0], bh[j][1]);
        #pragma unroll
        for (int i = 0; i < MF; i++)
            #pragma unroll
            for (int j = 0; j < NF; j++) mma16816(C[i][j], al[i], bh[j][0], bh[j][1]);
    }
}

// Variant: X already fp16 in smem.
template<int MF, int NF, int KT, int XP, int KPW>
__device__ __forceinline__ void gemm_ms16(const __half* __restrict__ Wh,
                                          const __half* __restrict__ Wl,
                                          const __half* __restrict__ Xs,
                                          float C[MF][NF][4], int m0, int n0, int lane) {
    const int lrow = (lane & 7) + ((lane >> 3) & 1) * 8;
    const int lk8  = ((lane >> 4) & 1) * 8;
    const int bn   = n0 + (lane >> 2);
    const int bk   = 2 * (lane & 3);
    for (int ks = 0; ks < KT/16; ks++) {
        u32 ah[MF][4], al[MF][4];
        #pragma unroll
        for (int i = 0; i < MF; i++) {
            int off = (m0 + i*16 + lrow)*KPW + ks*16 + lk8;
            ldsm4(ah[i], Wh + off);
            ldsm4(al[i], Wl + off);
        }
        u32 bh[NF][2];
        #pragma unroll
        for (int j = 0; j < NF; j++) {
            const __half* xp = Xs + (ks*16 + bk)*XP + bn + j*8;
            u16 x0 = __half_as_ushort(xp[0]),    x1 = __half_as_ushort(xp[XP]);
            u16 x2 = __half_as_ushort(xp[8*XP]), x3 = __half_as_ushort(xp[9*XP]);
            bh[j][0] = ((u32)x1 << 16) | x0;
            bh[j][1] = ((u32)x3 << 16) | x2;
        }
        #pragma unroll
        for (int i = 0; i < MF; i++)
            #pragma unroll
            for (int j = 0; j < NF; j++) mma16816(C[i][j], ah[i], bh[j][0], bh[j][1]);
        #pragma unroll
        for (int i = 0; i < MF; i++)
            #pragma unroll
            for (int j = 0; j < NF; j++) mma16816(C[i][j], al[i], bh[j][0], bh[j][1]);
    }
}

__device__ __forceinline__ void w_split(float w, __half* Wh, __half* Wl, int off) {
    __half h = __float2half_rn(w);
    Wh[off] = h;
    Wl[off] = __float2half_rn(w - __half2float(h));
}

// K1: coarse k,v. M=192, K=128, BN=32. 3-stage cp.async. fp16 outputs.
#define KV_SMEM (192*136*2*2 + 3*128*36*4 + 32*196*4)
__global__ void __launch_bounds__(256) k_kv(const float* __restrict__ hp,
        const float* __restrict__ Wk, const float* __restrict__ bk,
        const float* __restrict__ Wvp, const float* __restrict__ bvp) {
    extern __shared__ char smraw[];
    __half* Wh = (__half*)smraw;
    __half* Wl = Wh + 192*136;
    float* Xs = (float*)(smraw + 192*136*2*2);
    float* Ss = Xs + 3*128*36;
    int t = threadIdx.x;

    for (int idx = t; idx < 192*128; idx += 256) {
        int m = idx >> 7, k = idx & 127;
        float w = (m < 64) ? Wk[m*128 + k] : Wvp[(m - 64)*128 + k];
        w_split(w, Wh, Wl, m*136 + k);
    }
    const int NT = NPIX2/32;
    auto load_tile = [&](int buf, int tile) {
        float* X = Xs + buf*128*36;
        int p0 = tile*32, bb = p0 >> 15, s0 = p0 & (HW2 - 1);
        const float* hb = hp + (size_t)bb*128*HW2 + s0;
        #pragma unroll
        for (int c8 = 0; c8 < 4; c8++) {
            int chunk = t + 256*c8;
            int r = chunk >> 3, q = chunk & 7;
            cpa16(X + r*36 + q*4, hb + (size_t)r*HW2 + q*4);
        }
    };
    int lane = t & 31, warp = t >> 5;
    int wm = warp >> 1, wn = warp & 1;
    int m0 = wm*48, n0 = wn*16;
    int r0 = m0 + (lane >> 2);

    int tile = blockIdx.x, par = 0;
    if (tile < NT) load_tile(0, tile);
    CPA_COMMIT();
    if (tile + GRD < NT) load_tile(1, tile + GRD);
    CPA_COMMIT();
    __syncthreads();
    for (; tile < NT; tile += GRD) {
        int pre = tile + 2*GRD;
        if (pre < NT) load_tile((par + 2) % 3, pre);
        CPA_COMMIT();
        CPA_WAIT2();
        __syncthreads();

        float C[3][2][4];
        #pragma unroll
        for (int i = 0; i < 3; i++) {
            int ra = r0 + i*16, rb = ra + 8;
            float b0 = (ra < 64) ? bk[ra] : bvp[ra - 64];
            float b1 = (rb < 64) ? bk[rb] : bvp[rb - 64];
            #pragma unroll
            for (int j = 0; j < 2; j++) {
                C[i][j][0] = C[i][j][1] = b0;
                C[i][j][2] = C[i][j][3] = b1;
            }
        }
        gemm_ms<3,2,128,36,136>(Wh, Wl, Xs + par*128*36, C, m0, n0, lane);
        __syncthreads();
        #pragma unroll
        for (int i = 0; i < 3; i++)
            #pragma unroll
            for (int j = 0; j < 2; j++) {
                int pc = n0 + j*8 + 2*(lane & 3);
                int rr = m0 + i*16 + (lane >> 2);
                Ss[pc*196 + rr]           = C[i][j][0];
                Ss[(pc + 1)*196 + rr]     = C[i][j][1];
                Ss[pc*196 + rr + 8]       = C[i][j][2];
                Ss[(pc + 1)*196 + rr + 8] = C[i][j][3];
            }
        __syncthreads();
        int p0 = tile*32;
        #pragma unroll
        for (int c = 0; c < 2; c++) {
            int idx = t + 256*c;
            int p = idx >> 4, f4 = idx & 15;
            float4 v = *(const float4*)(Ss + p*196 + f4*4);
            u32 h0 = cvt2(v.y, v.x), h1 = cvt2(v.w, v.z);
            *(uint2*)(g_k16 + (size_t)(p0 + p)*64 + f4*4) = make_uint2(h0, h1);
        }
        #pragma unroll
        for (int c = 0; c < 4; c++) {
            int idx = t + 256*c;
            int p = idx >> 5, f5 = idx & 31;
            float4 v = *(const float4*)(Ss + p*196 + 64 + f5*4);
            u32 h0 = cvt2(v.y, v.x), h1 = cvt2(v.w, v.z);
            *(uint2*)(g_v16 + (size_t)(p0 + p)*128 + f5*4) = make_uint2(h0, h1);
        }
        __syncthreads();
        par = (par + 1) % 3;
    }
}

// K2: q. M=64, K=128, BN=128. 2-stage cp.async (round-10 proven). Outputs g_q16.
#define Q_SMEM (64*136*2*2 + 2*128*132*4 + 128*68*4)
__global__ void __launch_bounds__(256) k_q(const float* __restrict__ hi,
        const float* __restrict__ Wq, const float* __restrict__ bq) {
    extern __shared__ char smraw[];
    __half* Wh = (__half*)smraw;
    __half* Wl = Wh + 64*136;
    float* Xs = (float*)(smraw + 64*136*2*2);
    float* Ss = Xs + 2*128*132;
    int t = threadIdx.x;

    for (int idx = t; idx < 64*128; idx += 256) {
        int m = idx >> 7, k = idx & 127;
        w_split(Wq[idx], Wh, Wl, m*136 + k);
    }
    const int NT = NPIXF/128;
    auto load_tile = [&](int buf, int tile) {
        float* X = Xs + buf*128*132;
        int p0 = tile*128, bb = p0 >> 17, s0 = p0 & (HWF - 1);
        const float* hb = hi + (size_t)bb*128*HWF + s0;
        #pragma unroll
        for (int c8 = 0; c8 < 16; c8++) {
            int chunk = t + 256*c8;
            int r = chunk >> 5, q = chunk & 31;
            cpa16(X + r*132 + q*4, hb + (size_t)r*HWF + q*4);
        }
    };
    int lane = t & 31, warp = t >> 5;
    int wm = warp >> 2, wn = warp & 3;
    int m0 = wm*32, n0 = wn*32;
    int r0 = m0 + (lane >> 2);

    int tile = blockIdx.x, par = 0;
    if (tile < NT) load_tile(0, tile);
    CPA_COMMIT();
    __syncthreads();
    for (; tile < NT; tile += GRD) {
        int nxt = tile + GRD;
        if (nxt < NT) load_tile(par ^ 1, nxt);
        CPA_COMMIT();
        CPA_WAIT1();
        __syncthreads();

        float C[2][4][4];
        #pragma unroll
        for (int i = 0; i < 2; i++) {
            float b0 = bq[r0 + i*16], b1 = bq[r0 + i*16 + 8];
            #pragma unroll
            for (int j = 0; j < 4; j++) {
                C[i][j][0] = C[i][j][1] = b0;
                C[i][j][2] = C[i][j][3] = b1;
            }
        }
        gemm_ms<2,4,128,132,136>(Wh, Wl, Xs + par*128*132, C, m0, n0, lane);
        __syncthreads();
        #pragma unroll
        for (int i = 0; i < 2; i++)
            #pragma unroll
            for (int j = 0; j < 4; j++) {
                int pc = n0 + j*8 + 2*(lane & 3);
                int rr = m0 + i*16 + (lane >> 2);
                Ss[pc*68 + rr]           = C[i][j][0];
                Ss[(pc + 1)*68 + rr]     = C[i][j][1];
                Ss[pc*68 + rr + 8]       = C[i][j][2];
                Ss[(pc + 1)*68 + rr + 8] = C[i][j][3];
            }
        __syncthreads();
        int p0 = tile*128;
        #pragma unroll
        for (int c = 0; c < 8; c++) {
            int idx = t + 256*c;
            int p = idx >> 4, f4 = idx & 15;
            float4 v = *(const float4*)(Ss + p*68 + f4*4);
            u32 h0 = cvt2(v.y, v.x), h1 = cvt2(v.w, v.z);
            *(uint2*)(g_q16 + (size_t)(p0 + p)*64 + f4*4) = make_uint2(h0, h1);
        }
        __syncthreads();
        par ^= 1;
    }
}

// K3: attention. fp16 k/v/q in, fp16 x out. Phase B float4-vectorized.
#define ATTN_SMEM ((NH*KP + NH*VP + 256*AP)*4)
__global__ void __launch_bounds__(256) k_attn() {
    extern __shared__ float sm[];
    float* ks = sm;
    float* vs = ks + NH*KP;
    float* as = vs + NH*VP;
    int t = threadIdx.x;
    int b = blockIdx.z;
    int cy0 = blockIdx.y * CTY, cx0 = blockIdx.x * CTX;
    int fy0 = cy0*2, fx0 = cx0*2;

    for (int idx = t; idx < NH*8; idx += 256) {
        int pix = idx >> 3, c8 = idx & 7;
        int hy = pix / HX, hx = pix % HX;
        int gy = cy0 + hy - 1, gx = cx0 + hx - 1;
        float* d = ks + pix*KP + c8*8;
        if ((unsigned)gy < CH2 && (unsigned)gx < CW2) {
            uint4 v = *(const uint4*)(g_k16 + ((size_t)(b*HW2 + gy*CW2 + gx))*CCK + c8*8);
            float2 f0 = __half22float2(*reinterpret_cast<__half2*>(&v.x));
            float2 f1 = __half22float2(*reinterpret_cast<__half2*>(&v.y));
            float2 f2 = __half22float2(*reinterpret_cast<__half2*>(&v.z));
            float2 f3 = __half22float2(*reinterpret_cast<__half2*>(&v.w));
            d[0] = f0.x; d[1] = f0.y; d[2] = f1.x; d[3] = f1.y;
            d[4] = f2.x; d[5] = f2.y; d[6] = f3.x; d[7] = f3.y;
        } else {
            #pragma unroll
            for (int i = 0; i < 8; i++) d[i] = 0.f;
        }
    }
    for (int idx = t; idx < NH*16; idx += 256) {
        int pix = idx >> 4, c8 = idx & 15;
        int hy = pix / HX, hx = pix % HX;
        int gy = cy0 + hy - 1, gx = cx0 + hx - 1;
        float* d = vs + pix*VP + c8*8;
        if ((unsigned)gy < CH2 && (unsigned)gx < CW2) {
            uint4 v = *(const uint4*)(g_v16 + ((size_t)(b*HW2 + gy*CW2 + gx))*CC + c8*8);
            float2 f0 = __half22float2(*reinterpret_cast<__half2*>(&v.x));
            float2 f1 = __half22float2(*reinterpret_cast<__half2*>(&v.y));
            float2 f2 = __half22float2(*reinterpret_cast<__half2*>(&v.z));
            float2 f3 = __half22float2(*reinterpret_cast<__half2*>(&v.w));
            d[0] = f0.x; d[1] = f0.y; d[2] = f1.x; d[3] = f1.y;
            d[4] = f2.x; d[5] = f2.y; d[6] = f3.x; d[7] = f3.y;
        } else {
            #pragma unroll
            for (int i = 0; i < 8; i++) d[i] = 0.f;
        }
    }
    __syncthreads();

    {   // Phase A
        int p = t;
        int fy = p >> 5, fx = p & 31;
        int cy = fy >> 1, cx = fx >> 1;
        const uint4* gq = reinterpret_cast<const uint4*>(
            g_q16 + ((size_t)((b*CH + fy0 + fy)*CW + fx0 + fx))*CCK);
        const float* kb = ks + (cy*HX + cx)*KP;
        ull sc2[9];
        #pragma unroll
        for (int j = 0; j < 9; j++) sc2[j] = 0ull;
        #pragma unroll 2
        for (int cc = 0; cc < 8; cc++) {
            uint4 qv = gq[cc];
            float2 f0 = __half22float2(*reinterpret_cast<__half2*>(&qv.x));
            float2 f1 = __half22float2(*reinterpret_cast<__half2*>(&qv.y));
            float2 f2 = __half22float2(*reinterpret_cast<__half2*>(&qv.z));
            float2 f3 = __half22float2(*reinterpret_cast<__half2*>(&qv.w));
            ull q0 = pk2p(f0.x, f0.y), q1 = pk2p(f1.x, f1.y);
            ull q2 = pk2p(f2.x, f2.y), q3 = pk2p(f3.x, f3.y);
            int c = cc*8;
            #pragma unroll
            for (int dy = 0; dy < 3; dy++)
                #pragma unroll
                for (int dx = 0; dx < 3; dx++) {
                    int j = dy*3 + dx;
                    const float* kp = kb + (dy*HX + dx)*KP + c;
                    sc2[j] = fma2(q0, ld2(kp),     sc2[j]);
                    sc2[j] = fma2(q1, ld2(kp + 2), sc2[j]);
                    sc2[j] = fma2(q2, ld2(kp + 4), sc2[j]);
                    sc2[j] = fma2(q3, ld2(kp + 6), sc2[j]);
                }
        }
        float sc[9];
        #pragma unroll
        for (int j = 0; j < 9; j++) { float2 v = upk(sc2[j]); sc[j] = v.x + v.y; }
        float m = sc[0];
        #pragma unroll
        for (int j = 1; j < 9; j++) m = fmaxf(m, sc[j]);
        float s = 0.f;
        #pragma unroll
        for (int j = 0; j < 9; j++) { sc[j] = __expf(sc[j] - m); s += sc[j]; }
        float inv = 1.f / s;
        #pragma unroll
        for (int j = 0; j < 9; j++) as[p*AP + j] = sc[j]*inv;
    }
    __syncthreads();

    {   // Phase B: float4 v loads, 4 channels per iteration
        int cell = t & 63, cg = t >> 6;
        int cyl = cell >> 4, cxl = cell & 15;
        ull a01[9], a23[9];
        int p00 = (2*cyl)*32 + 2*cxl;
        int p10 = p00 + 32;
        #pragma unroll
        for (int j = 0; j < 9; j++) {
            a01[j] = pk2p(as[p00*AP + j], as[(p00 + 1)*AP + j]);
            a23[j] = pk2p(as[p10*AP + j], as[(p10 + 1)*AP + j]);
        }
        const float* vb = vs + (cyl*HX + cxl)*VP + cg*32;
        size_t obase = ((size_t)(b*CC + cg*32))*HWF
                     + (size_t)(fy0 + 2*cyl)*CW + fx0 + 2*cxl;
        #pragma unroll 2
        for (int c4 = 0; c4 < 8; c4++) {
            ull o01[4] = {0ull, 0ull, 0ull, 0ull};
            ull o23[4] = {0ull, 0ull, 0ull, 0ull};
            #pragma unroll
            for (int dy = 0; dy < 3; dy++)
                #pragma unroll
                for (int dx = 0; dx < 3; dx++) {
                    int j = dy*3 + dx;
                    float4 vv = *(const float4*)(vb + (dy*HX + dx)*VP + c4*4);
                    o01[0] = fma2(a01[j], pk2(vv.x), o01[0]);
                    o01[1] = fma2(a01[j], pk2(vv.y), o01[1]);
                    o01[2] = fma2(a01[j], pk2(vv.z), o01[2]);
                    o01[3] = fma2(a01[j], pk2(vv.w), o01[3]);
                    o23[0] = fma2(a23[j], pk2(vv.x), o23[0]);
                    o23[1] = fma2(a23[j], pk2(vv.y), o23[1]);
                    o23[2] = fma2(a23[j], pk2(vv.z), o23[2]);
                    o23[3] = fma2(a23[j], pk2(vv.w), o23[3]);
                }
            #pragma unroll
            for (int e = 0; e < 4; e++) {
                float2 r01 = upk(o01[e]), r23 = upk(o23[e]);
                size_t oa = obase + (size_t)(c4*4 + e)*HWF;
                *reinterpret_cast<u32*>(g_x16 + oa)      = cvt2(r01.y, r01.x);
                *reinterpret_cast<u32*>(g_x16 + oa + CW) = cvt2(r23.y, r23.x);
            }
        }
    }
}

// K4: out. M=128, K=256 as two K=128 passes (h fp32, x fp16). BN=32.
// 3-stage cp.async pipeline.
#define XP16 40
#define O_W_BYTES  (128*264*2*2)
#define O_STG32    (128*36*4)
#define O_X16_OFF  (O_W_BYTES + 3*O_STG32)
#define O_STG16    (128*XP16*2)
#define O_SMEM     (O_X16_OFF + 3*O_STG16)
__global__ void __launch_bounds__(256) k_out(const float* __restrict__ hi,
        const float* __restrict__ Wout, float* __restrict__ out) {
    extern __shared__ char smraw[];
    __half* Wh = (__half*)smraw;
    __half* Wl = Wh + 128*264;
    float* Xs32 = (float*)(smraw + O_W_BYTES);
    __half* Xs16 = (__half*)(smraw + O_X16_OFF);
    int t = threadIdx.x;

    for (int idx = t; idx < 128*256; idx += 256) {
        int m = idx >> 8, k = idx & 255;
        float w = (k < 128) ? g_Wc[m*128 + k] : Wout[m*128 + (k - 128)];
        w_split(w, Wh, Wl, m*264 + k);
    }
    const int NT = NPIXF/32;
    auto load_tile = [&](int buf, int tile) {
        float* X = Xs32 + buf*128*36;
        __half* X6 = Xs16 + buf*128*XP16;
        int p0 = tile*32, bb = p0 >> 17, s0 = p0 & (HWF - 1);
        const float* hb = hi + (size_t)bb*128*HWF + s0;
        const __half* xb = g_x16 + (size_t)bb*128*HWF + s0;
        #pragma unroll
        for (int c8 = 0; c8 < 4; c8++) {
            int chunk = t + 256*c8;
            int r = chunk >> 3, q = chunk & 7;
            cpa16(X + r*36 + q*4, hb + (size_t)r*HWF + q*4);
        }
        #pragma unroll
        for (int c8 = 0; c8 < 2; c8++) {
            int chunk = t + 256*c8;
            int r = chunk >> 2, q = chunk & 3;
            cpa16(X6 + r*XP16 + q*8, xb + (size_t)r*HWF + q*8);
        }
    };
    int lane = t & 31, warp = t >> 5;
    int wm = warp >> 1, wn = warp & 1;
    int m0 = wm*32, n0 = wn*16;
    int r0 = m0 + (lane >> 2);

    int tile = blockIdx.x, par = 0;
    if (tile < NT) load_tile(0, tile);
    CPA_COMMIT();
    if (tile + GRD < NT) load_tile(1, tile + GRD);
    CPA_COMMIT();
    __syncthreads();
    for (; tile < NT; tile += GRD) {
        int pre = tile + 2*GRD;
        if (pre < NT) load_tile((par + 2) % 3, pre);
        CPA_COMMIT();
        CPA_WAIT2();
        __syncthreads();

        float C[2][2][4];
        #pragma unroll
        for (int i = 0; i < 2; i++) {
            float b0 = g_beff[r0 + i*16], b1 = g_beff[r0 + i*16 + 8];
            #pragma unroll
            for (int j = 0; j < 2; j++) {
                C[i][j][0] = C[i][j][1] = b0;
                C[i][j][2] = C[i][j][3] = b1;
            }
        }
        gemm_ms<2,2,128,36,264>(Wh, Wl, Xs32 + par*128*36, C, m0, n0, lane);
        gemm_ms16<2,2,128,XP16,264>(Wh + 128, Wl + 128, Xs16 + par*128*XP16, C, m0, n0, lane);

        int p0 = tile*32, bb = p0 >> 17, s0 = p0 & (HWF - 1);
        float* ob = out + (size_t)bb*128*HWF + s0;
        int cb = n0 + 2*(lane & 3);
        #pragma unroll
        for (int i = 0; i < 2; i++) {
            int r = r0 + i*16;
            #pragma unroll
            for (int j = 0; j < 2; j++) {
                int ccol = cb + j*8;
                *(float2*)(ob + (size_t)r*HWF + ccol)       = make_float2(C[i][j][0], C[i][j][1]);
                *(float2*)(ob + (size_t)(r + 8)*HWF + ccol) = make_float2(C[i][j][2], C[i][j][3]);
            }
        }
        __syncthreads();
        par = (par + 1) % 3;
    }
}

extern "C" void kernel_launch(void* const* d_in, const int* in_sizes, int n_in,
                              void* d_out, int out_size) {
    const float* h_prev = (const float*)d_in[0];
    const float* h_init = (const float*)d_in[1];
    const float* Wq   = (const float*)d_in[2];
    const float* bq   = (const float*)d_in[3];
    const float* Wk   = (const float*)d_in[4];
    const float* bk   = (const float*)d_in[5];
    const float* Wvp  = (const float*)d_in[6];
    const float* bvp  = (const float*)d_in[7];
    const float* Wvi  = (const float*)d_in[8];
    const float* bvi  = (const float*)d_in[9];
    const float* Wout = (const float*)d_in[10];
    const float* bout = (const float*)d_in[11];
    float* out = (float*)d_out;

    cudaFuncSetAttribute(k_kv,   cudaFuncAttributeMaxDynamicSharedMemorySize, KV_SMEM);
    cudaFuncSetAttribute(k_q,    cudaFuncAttributeMaxDynamicSharedMemorySize, Q_SMEM);
    cudaFuncSetAttribute(k_attn, cudaFuncAttributeMaxDynamicSharedMemorySize, ATTN_SMEM);
    cudaFuncSetAttribute(k_out,  cudaFuncAttributeMaxDynamicSharedMemorySize, O_SMEM);

    k_fuse<<<CC, CC>>>(Wout, Wvi, bvi, bout);
    k_kv<<<GRD, 256, KV_SMEM>>>(h_prev, Wk, bk, Wvp, bvp);
    k_q<<<GRD, 256, Q_SMEM>>>(h_init, Wq, bq);
    dim3 ag(CW2/CTX, CH2/CTY, CB);
    k_attn<<<ag, 256, ATTN_SMEM>>>();
    k_out<<<GRD, 256, O_SMEM>>>(h_init, Wout, out);
}

// round 14
// speedup vs baseline: 2.4613x; 1.0910x over previous
#include <cuda_runtime.h>
#include <cuda_fp16.h>
#include <cstdint>

#define CB 2
#define CC 128
#define CCK 64
#define CH 256
#define CW 512
#define CH2 128
#define CW2 256
#define HWF (CH*CW)
#define HW2 (CH2*CW2)
#define NPIXF (CB*HWF)
#define NPIX2 (CB*HW2)
#define GRD 148

#define CTY 4
#define CTX 16
#define HX 18
#define NH 108
#define KP 66
#define VP 132
#define AP 13

typedef unsigned long long ull;
typedef unsigned int u32;
typedef unsigned short u16;

__device__ __forceinline__ ull fma2(ull a, ull b, ull c) {
    ull d; asm("fma.rn.f32x2 %0, %1, %2, %3;" : "=l"(d) : "l"(a), "l"(b), "l"(c)); return d;
}
__device__ __forceinline__ ull pk2(float x) {
    ull r; asm("mov.b64 %0, {%1, %1};" : "=l"(r) : "f"(x)); return r;
}
__device__ __forceinline__ ull pk2p(float x, float y) {
    ull r; asm("mov.b64 %0, {%1, %2};" : "=l"(r) : "f"(x), "f"(y)); return r;
}
__device__ __forceinline__ float2 upk(ull v) {
    float2 o; asm("mov.b64 {%0, %1}, %2;" : "=f"(o.x), "=f"(o.y) : "l"(v)); return o;
}
__device__ __forceinline__ ull ld2(const float* p) { return *reinterpret_cast<const ull*>(p); }

__device__ __forceinline__ void ldsm4(u32* r, const __half* p) {
    u32 sa = (u32)__cvta_generic_to_shared(p);
    asm volatile("ldmatrix.sync.aligned.m8n8.x4.shared.b16 {%0,%1,%2,%3}, [%4];"
        : "=r"(r[0]), "=r"(r[1]), "=r"(r[2]), "=r"(r[3]) : "r"(sa));
}
__device__ __forceinline__ void mma16816(float* c, const u32* a, u32 b0, u32 b1) {
    asm volatile("mma.sync.aligned.m16n8k16.row.col.f32.f16.f16.f32 "
        "{%0,%1,%2,%3}, {%4,%5,%6,%7}, {%8,%9}, {%0,%1,%2,%3};"
        : "+f"(c[0]), "+f"(c[1]), "+f"(c[2]), "+f"(c[3])
        : "r"(a[0]), "r"(a[1]), "r"(a[2]), "r"(a[3]), "r"(b0), "r"(b1));
}
__device__ __forceinline__ u32 cvt2(float hiF, float loF) {
    u32 r; asm("cvt.rn.f16x2.f32 %0, %1, %2;" : "=r"(r) : "f"(hiF), "f"(loF)); return r;
}
__device__ __forceinline__ void cpa16(void* dst, const void* src) {
    u32 d = (u32)__cvta_generic_to_shared(dst);
    asm volatile("cp.async.cg.shared.global [%0], [%1], 16;" :: "r"(d), "l"(src));
}
#define CPA_COMMIT() asm volatile("cp.async.commit_group;")
#define CPA_WAIT1()  asm volatile("cp.async.wait_group 1;")

__device__ __half g_k16[(size_t)NPIX2*CCK];
__device__ __half g_v16[(size_t)NPIX2*CC];
__device__ __half g_q16[(size_t)NPIXF*CCK];
__device__ __half g_p16[(size_t)NPIXF*CC];   // partial = Wc@h + beff, NCHW fp16
__device__ __half g_x16[(size_t)NPIXF*CC];   // NCHW fp16
__device__ float  g_Wc[CC*CC];
__device__ float  g_beff[CC];

__global__ void k_fuse(const float* __restrict__ Wout, const float* __restrict__ Wvi,
                       const float* __restrict__ bvi, const float* __restrict__ bout) {
    int o = blockIdx.x, i = threadIdx.x;
    float acc = 0.f;
    for (int m = 0; m < CC; m++) acc += Wout[o*CC + m] * Wvi[m*CC + i];
    g_Wc[o*CC + i] = acc;
    if (i == 0) {
        float b = bout[o];
        for (int m = 0; m < CC; m++) b += Wout[o*CC + m] * bvi[m];
        g_beff[o] = b;
    }
}

// fp16 2-product GEMM mainloop: W split (hi+lo fp16), X fp32 smem -> fp16 frag.
template<int MF, int NF, int KT, int XP, int KPW>
__device__ __forceinline__ void gemm_ms(const __half* __restrict__ Wh,
                                        const __half* __restrict__ Wl,
                                        const float* __restrict__ Xs,
                                        float C[MF][NF][4], int m0, int n0, int lane) {
    const int lrow = (lane & 7) + ((lane >> 3) & 1) * 8;
    const int lk8  = ((lane >> 4) & 1) * 8;
    const int bn   = n0 + (lane >> 2);
    const int bk   = 2 * (lane & 3);
    for (int ks = 0; ks < KT/16; ks++) {
        u32 ah[MF][4], al[MF][4];
        #pragma unroll
        for (int i = 0; i < MF; i++) {
            int off = (m0 + i*16 + lrow)*KPW + ks*16 + lk8;
            ldsm4(ah[i], Wh + off);
            ldsm4(al[i], Wl + off);
        }
        u32 bh[NF][2];
        #pragma unroll
        for (int j = 0; j < NF; j++) {
            const float* xp = Xs + (ks*16 + bk)*XP + bn + j*8;
            float x0 = xp[0], x1 = xp[XP], x2 = xp[8*XP], x3 = xp[9*XP];
            bh[j][0] = cvt2(x1, x0);
            bh[j][1] = cvt2(x3, x2);
        }
        #pragma unroll
        for (int i = 0; i < MF; i++)
            #pragma unroll
            for (int j = 0; j < NF; j++) mma16816(C[i][j], ah[i], bh[j][0], bh[j][1]);
        #pragma unroll
        for (int i = 0; i < MF; i++)
            #pragma unroll
            for (int j = 0; j < NF; j++) mma16816(C[i][j], al[i], bh[j][0], bh[j][1]);
    }
}

// Variant: X already fp16 in smem.
template<int MF, int NF, int KT, int XP, int KPW>
__device__ __forceinline__ void gemm_ms16(const __half* __restrict__ Wh,
                                          const __half* __restrict__ Wl,
                                          const __half* __restrict__ Xs,
                                          float C[MF][NF][4], int m0, int n0, int lane) {
    const int lrow = (lane & 7) + ((lane >> 3) & 1) * 8;
    const int lk8  = ((lane >> 4) & 1) * 8;
    const int bn   = n0 + (lane >> 2);
    const int bk   = 2 * (lane & 3);
    for (int ks = 0; ks < KT/16; ks++) {
        u32 ah[MF][4], al[MF][4];
        #pragma unroll
        for (int i = 0; i < MF; i++) {
            int off = (m0 + i*16 + lrow)*KPW + ks*16 + lk8;
            ldsm4(ah[i], Wh + off);
            ldsm4(al[i], Wl + off);
        }
        u32 bh[NF][2];
        #pragma unroll
        for (int j = 0; j < NF; j++) {
            const __half* xp = Xs + (ks*16 + bk)*XP + bn + j*8;
            u16 x0 = __half_as_ushort(xp[0]),    x1 = __half_as_ushort(xp[XP]);
            u16 x2 = __half_as_ushort(xp[8*XP]), x3 = __half_as_ushort(xp[9*XP]);
            bh[j][0] = ((u32)x1 << 16) | x0;
            bh[j][1] = ((u32)x3 << 16) | x2;
        }
        #pragma unroll
        for (int i = 0; i < MF; i++)
            #pragma unroll
            for (int j = 0; j < NF; j++) mma16816(C[i][j], ah[i], bh[j][0], bh[j][1]);
        #pragma unroll
        for (int i = 0; i < MF; i++)
            #pragma unroll
            for (int j = 0; j < NF; j++) mma16816(C[i][j], al[i], bh[j][0], bh[j][1]);
    }
}

__device__ __forceinline__ void w_split(float w, __half* Wh, __half* Wl, int off) {
    __half h = __float2half_rn(w);
    Wh[off] = h;
    Wl[off] = __float2half_rn(w - __half2float(h));
}

// K1: coarse k,v. M=192, K=128, BN=32. 2-stage cp.async. fp16 outputs.
#define KV_SMEM (192*136*2*2 + 2*128*36*4 + 32*196*4)
__global__ void __launch_bounds__(256) k_kv(const float* __restrict__ hp,
        const float* __restrict__ Wk, const float* __restrict__ bk,
        const float* __restrict__ Wvp, const float* __restrict__ bvp) {
    extern __shared__ char smraw[];
    __half* Wh = (__half*)smraw;
    __half* Wl = Wh + 192*136;
    float* Xs = (float*)(smraw + 192*136*2*2);
    float* Ss = Xs + 2*128*36;
    int t = threadIdx.x;

    for (int idx = t; idx < 192*128; idx += 256) {
        int m = idx >> 7, k = idx & 127;
        float w = (m < 64) ? Wk[m*128 + k] : Wvp[(m - 64)*128 + k];
        w_split(w, Wh, Wl, m*136 + k);
    }
    const int NT = NPIX2/32;
    auto load_tile = [&](int buf, int tile) {
        float* X = Xs + buf*128*36;
        int p0 = tile*32, bb = p0 >> 15, s0 = p0 & (HW2 - 1);
        const float* hb = hp + (size_t)bb*128*HW2 + s0;
        #pragma unroll
        for (int c8 = 0; c8 < 4; c8++) {
            int chunk = t + 256*c8;
            int r = chunk >> 3, q = chunk & 7;
            cpa16(X + r*36 + q*4, hb + (size_t)r*HW2 + q*4);
        }
    };
    int lane = t & 31, warp = t >> 5;
    int wm = warp >> 1, wn = warp & 1;
    int m0 = wm*48, n0 = wn*16;
    int r0 = m0 + (lane >> 2);

    int tile = blockIdx.x, par = 0;
    if (tile < NT) load_tile(0, tile);
    CPA_COMMIT();
    __syncthreads();
    for (; tile < NT; tile += GRD) {
        int nxt = tile + GRD;
        if (nxt < NT) load_tile(par ^ 1, nxt);
        CPA_COMMIT();
        CPA_WAIT1();
        __syncthreads();

        float C[3][2][4];
        #pragma unroll
        for (int i = 0; i < 3; i++) {
            int ra = r0 + i*16, rb = ra + 8;
            float b0 = (ra < 64) ? bk[ra] : bvp[ra - 64];
            float b1 = (rb < 64) ? bk[rb] : bvp[rb - 64];
            #pragma unroll
            for (int j = 0; j < 2; j++) {
                C[i][j][0] = C[i][j][1] = b0;
                C[i][j][2] = C[i][j][3] = b1;
            }
        }
        gemm_ms<3,2,128,36,136>(Wh, Wl, Xs + par*128*36, C, m0, n0, lane);
        __syncthreads();
        #pragma unroll
        for (int i = 0; i < 3; i++)
            #pragma unroll
            for (int j = 0; j < 2; j++) {
                int pc = n0 + j*8 + 2*(lane & 3);
                int rr = m0 + i*16 + (lane >> 2);
                Ss[pc*196 + rr]           = C[i][j][0];
                Ss[(pc + 1)*196 + rr]     = C[i][j][1];
                Ss[pc*196 + rr + 8]       = C[i][j][2];
                Ss[(pc + 1)*196 + rr + 8] = C[i][j][3];
            }
        __syncthreads();
        int p0 = tile*32;
        #pragma unroll
        for (int c = 0; c < 2; c++) {
            int idx = t + 256*c;
            int p = idx >> 4, f4 = idx & 15;
            float4 v = *(const float4*)(Ss + p*196 + f4*4);
            u32 h0 = cvt2(v.y, v.x), h1 = cvt2(v.w, v.z);
            *(uint2*)(g_k16 + (size_t)(p0 + p)*64 + f4*4) = make_uint2(h0, h1);
        }
        #pragma unroll
        for (int c = 0; c < 4; c++) {
            int idx = t + 256*c;
            int p = idx >> 5, f5 = idx & 31;
            float4 v = *(const float4*)(Ss + p*196 + 64 + f5*4);
            u32 h0 = cvt2(v.y, v.x), h1 = cvt2(v.w, v.z);
            *(uint2*)(g_v16 + (size_t)(p0 + p)*128 + f5*4) = make_uint2(h0, h1);
        }
        __syncthreads();
        par ^= 1;
    }
}

// K2: merged q + partial: [Wc(128); Wq(64)] @ h_init. M=192, K=128, BN=64.
// Rows 0-127 -> g_p16 (NCHW direct); rows 128-191 -> g_q16 (NHWC via Ss).
#define QP_SMEM (192*136*2*2 + 2*128*68*4 + 64*68*4)
__global__ void __launch_bounds__(256) k_qp(const float* __restrict__ hi,
        const float* __restrict__ Wq, const float* __restrict__ bq) {
    extern __shared__ char smraw[];
    __half* Wh = (__half*)smraw;
    __half* Wl = Wh + 192*136;
    float* Xs = (float*)(smraw + 192*136*2*2);
    float* Ss = Xs + 2*128*68;
    int t = threadIdx.x;

    for (int idx = t; idx < 192*128; idx += 256) {
        int m = idx >> 7, k = idx & 127;
        float w = (m < 128) ? g_Wc[m*128 + k] : Wq[(m - 128)*128 + k];
        w_split(w, Wh, Wl, m*136 + k);
    }
    const int NT = NPIXF/64;
    auto load_tile = [&](int buf, int tile) {
        float* X = Xs + buf*128*68;
        int p0 = tile*64, bb = p0 >> 17, s0 = p0 & (HWF - 1);
        const float* hb = hi + (size_t)bb*128*HWF + s0;
        #pragma unroll
        for (int c8 = 0; c8 < 8; c8++) {
            int chunk = t + 256*c8;
            int r = chunk >> 4, q = chunk & 15;
            cpa16(X + r*68 + q*4, hb + (size_t)r*HWF + q*4);
        }
    };
    int lane = t & 31, warp = t >> 5;
    int wm = warp >> 1, wn = warp & 1;       // 4 x 2 warps: M=48/warp, N=32/warp
    int m0 = wm*48, n0 = wn*32;
    int r0 = m0 + (lane >> 2);

    int tile = blockIdx.x, par = 0;
    if (tile < NT) load_tile(0, tile);
    CPA_COMMIT();
    __syncthreads();
    for (; tile < NT; tile += GRD) {
        int nxt = tile + GRD;
        if (nxt < NT) load_tile(par ^ 1, nxt);
        CPA_COMMIT();
        CPA_WAIT1();
        __syncthreads();

        float C[3][4][4];
        #pragma unroll
        for (int i = 0; i < 3; i++) {
            int ra = r0 + i*16, rb = ra + 8;
            float b0 = (ra < 128) ? g_beff[ra] : bq[ra - 128];
            float b1 = (rb < 128) ? g_beff[rb] : bq[rb - 128];
            #pragma unroll
            for (int j = 0; j < 4; j++) {
                C[i][j][0] = C[i][j][1] = b0;
                C[i][j][2] = C[i][j][3] = b1;
            }
        }
        gemm_ms<3,4,128,68,136>(Wh, Wl, Xs + par*128*68, C, m0, n0, lane);

        int p0 = tile*64, bb = p0 >> 17, s0 = p0 & (HWF - 1);
        __half* pb = g_p16 + (size_t)bb*128*HWF + s0;
        #pragma unroll
        for (int i = 0; i < 3; i++) {
            int row16 = m0 + i*16;
            int rr = row16 + (lane >> 2);
            int pcb = n0 + 2*(lane & 3);
            if (row16 < 128) {
                #pragma unroll
                for (int j = 0; j < 4; j++) {
                    int pc = pcb + j*8;
                    *(u32*)(pb + (size_t)rr*HWF + pc)       = cvt2(C[i][j][1], C[i][j][0]);
                    *(u32*)(pb + (size_t)(rr + 8)*HWF + pc) = cvt2(C[i][j][3], C[i][j][2]);
                }
            } else {
                int rq = rr - 128;
                #pragma unroll
                for (int j = 0; j < 4; j++) {
                    int pc = pcb + j*8;
                    Ss[pc*68 + rq]           = C[i][j][0];
                    Ss[(pc + 1)*68 + rq]     = C[i][j][1];
                    Ss[pc*68 + rq + 8]       = C[i][j][2];
                    Ss[(pc + 1)*68 + rq + 8] = C[i][j][3];
                }
            }
        }
        __syncthreads();
        #pragma unroll
        for (int c = 0; c < 4; c++) {
            int idx = t + 256*c;
            int p = idx >> 4, f4 = idx & 15;
            float4 v = *(const float4*)(Ss + p*68 + f4*4);
            u32 h0 = cvt2(v.y, v.x), h1 = cvt2(v.w, v.z);
            *(uint2*)(g_q16 + (size_t)(p0 + p)*64 + f4*4) = make_uint2(h0, h1);
        }
        __syncthreads();
        par ^= 1;
    }
}

// K3: attention. fp16 k/v/q in, fp16 x out. Phase B float4-vectorized.
#define ATTN_SMEM ((NH*KP + NH*VP + 256*AP)*4)
__global__ void __launch_bounds__(256) k_attn() {
    extern __shared__ float sm[];
    float* ks = sm;
    float* vs = ks + NH*KP;
    float* as = vs + NH*VP;
    int t = threadIdx.x;
    int b = blockIdx.z;
    int cy0 = blockIdx.y * CTY, cx0 = blockIdx.x * CTX;
    int fy0 = cy0*2, fx0 = cx0*2;

    for (int idx = t; idx < NH*8; idx += 256) {
        int pix = idx >> 3, c8 = idx & 7;
        int hy = pix / HX, hx = pix % HX;
        int gy = cy0 + hy - 1, gx = cx0 + hx - 1;
        float* d = ks + pix*KP + c8*8;
        if ((unsigned)gy < CH2 && (unsigned)gx < CW2) {
            uint4 v = *(const uint4*)(g_k16 + ((size_t)(b*HW2 + gy*CW2 + gx))*CCK + c8*8);
            float2 f0 = __half22float2(*reinterpret_cast<__half2*>(&v.x));
            float2 f1 = __half22float2(*reinterpret_cast<__half2*>(&v.y));
            float2 f2 = __half22float2(*reinterpret_cast<__half2*>(&v.z));
            float2 f3 = __half22float2(*reinterpret_cast<__half2*>(&v.w));
            d[0] = f0.x; d[1] = f0.y; d[2] = f1.x; d[3] = f1.y;
            d[4] = f2.x; d[5] = f2.y; d[6] = f3.x; d[7] = f3.y;
        } else {
            #pragma unroll
            for (int i = 0; i < 8; i++) d[i] = 0.f;
        }
    }
    for (int idx = t; idx < NH*16; idx += 256) {
        int pix = idx >> 4, c8 = idx & 15;
        int hy = pix / HX, hx = pix % HX;
        int gy = cy0 + hy - 1, gx = cx0 + hx - 1;
        float* d = vs + pix*VP + c8*8;
        if ((unsigned)gy < CH2 && (unsigned)gx < CW2) {
            uint4 v = *(const uint4*)(g_v16 + ((size_t)(b*HW2 + gy*CW2 + gx))*CC + c8*8);
            float2 f0 = __half22float2(*reinterpret_cast<__half2*>(&v.x));
            float2 f1 = __half22float2(*reinterpret_cast<__half2*>(&v.y));
            float2 f2 = __half22float2(*reinterpret_cast<__half2*>(&v.z));
            float2 f3 = __half22float2(*reinterpret_cast<__half2*>(&v.w));
            d[0] = f0.x; d[1] = f0.y; d[2] = f1.x; d[3] = f1.y;
            d[4] = f2.x; d[5] = f2.y; d[6] = f3.x; d[7] = f3.y;
        } else {
            #pragma unroll
            for (int i = 0; i < 8; i++) d[i] = 0.f;
        }
    }
    __syncthreads();

    {   // Phase A
        int p = t;
        int fy = p >> 5, fx = p & 31;
        int cy = fy >> 1, cx = fx >> 1;
        const uint4* gq = reinterpret_cast<const uint4*>(
            g_q16 + ((size_t)((b*CH + fy0 + fy)*CW + fx0 + fx))*CCK);
        const float* kb = ks + (cy*HX + cx)*KP;
        ull sc2[9];
        #pragma unroll
        for (int j = 0; j < 9; j++) sc2[j] = 0ull;
        #pragma unroll 2
        for (int cc = 0; cc < 8; cc++) {
            uint4 qv = gq[cc];
            float2 f0 = __half22float2(*reinterpret_cast<__half2*>(&qv.x));
            float2 f1 = __half22float2(*reinterpret_cast<__half2*>(&qv.y));
            float2 f2 = __half22float2(*reinterpret_cast<__half2*>(&qv.z));
            float2 f3 = __half22float2(*reinterpret_cast<__half2*>(&qv.w));
            ull q0 = pk2p(f0.x, f0.y), q1 = pk2p(f1.x, f1.y);
            ull q2 = pk2p(f2.x, f2.y), q3 = pk2p(f3.x, f3.y);
            int c = cc*8;
            #pragma unroll
            for (int dy = 0; dy < 3; dy++)
                #pragma unroll
                for (int dx = 0; dx < 3; dx++) {
                    int j = dy*3 + dx;
                    const float* kp = kb + (dy*HX + dx)*KP + c;
                    sc2[j] = fma2(q0, ld2(kp),     sc2[j]);
                    sc2[j] = fma2(q1, ld2(kp + 2), sc2[j]);
                    sc2[j] = fma2(q2, ld2(kp + 4), sc2[j]);
                    sc2[j] = fma2(q3, ld2(kp + 6), sc2[j]);
                }
        }
        float sc[9];
        #pragma unroll
        for (int j = 0; j < 9; j++) { float2 v = upk(sc2[j]); sc[j] = v.x + v.y; }
        float m = sc[0];
        #pragma unroll
        for (int j = 1; j < 9; j++) m = fmaxf(m, sc[j]);
        float s = 0.f;
        #pragma unroll
        for (int j = 0; j < 9; j++) { sc[j] = __expf(sc[j] - m); s += sc[j]; }
        float inv = 1.f / s;
        #pragma unroll
        for (int j = 0; j < 9; j++) as[p*AP + j] = sc[j]*inv;
    }
    __syncthreads();

    {   // Phase B: float4 v loads, 4 channels per iteration
        int cell = t & 63, cg = t >> 6;
        int cyl = cell >> 4, cxl = cell & 15;
        ull a01[9], a23[9];
        int p00 = (2*cyl)*32 + 2*cxl;
        int p10 = p00 + 32;
        #pragma unroll
        for (int j = 0; j < 9; j++) {
            a01[j] = pk2p(as[p00*AP + j], as[(p00 + 1)*AP + j]);
            a23[j] = pk2p(as[p10*AP + j], as[(p10 + 1)*AP + j]);
        }
        const float* vb = vs + (cyl*HX + cxl)*VP + cg*32;
        size_t obase = ((size_t)(b*CC + cg*32))*HWF
                     + (size_t)(fy0 + 2*cyl)*CW + fx0 + 2*cxl;
        #pragma unroll 2
        for (int c4 = 0; c4 < 8; c4++) {
            ull o01[4] = {0ull, 0ull, 0ull, 0ull};
            ull o23[4] = {0ull, 0ull, 0ull, 0ull};
            #pragma unroll
            for (int dy = 0; dy < 3; dy++)
                #pragma unroll
                for (int dx = 0; dx < 3; dx++) {
                    int j = dy*3 + dx;
                    float4 vv = *(const float4*)(vb + (dy*HX + dx)*VP + c4*4);
                    o01[0] = fma2(a01[j], pk2(vv.x), o01[0]);
                    o01[1] = fma2(a01[j], pk2(vv.y), o01[1]);
                    o01[2] = fma2(a01[j], pk2(vv.z), o01[2]);
                    o01[3] = fma2(a01[j], pk2(vv.w), o01[3]);
                    o23[0] = fma2(a23[j], pk2(vv.x), o23[0]);
                    o23[1] = fma2(a23[j], pk2(vv.y), o23[1]);
                    o23[2] = fma2(a23[j], pk2(vv.z), o23[2]);
                    o23[3] = fma2(a23[j], pk2(vv.w), o23[3]);
                }
            #pragma unroll
            for (int e = 0; e < 4; e++) {
                float2 r01 = upk(o01[e]), r23 = upk(o23[e]);
                size_t oa = obase + (size_t)(c4*4 + e)*HWF;
                *reinterpret_cast<u32*>(g_x16 + oa)      = cvt2(r01.y, r01.x);
                *reinterpret_cast<u32*>(g_x16 + oa + CW) = cvt2(r23.y, r23.x);
            }
        }
    }
}

// K4: out = p + Wout@x. M=128, K=128, BN=32. fp16 staging of p16 + x16.
#define XP16 40
#define O_SMEM (128*136*2*2 + 4*128*XP16*2)
__global__ void __launch_bounds__(256) k_out(const float* __restrict__ Wout,
        float* __restrict__ out) {
    extern __shared__ char smraw[];
    __half* Wh = (__half*)smraw;
    __half* Wl = Wh + 128*136;
    __half* Xp = (__half*)(smraw + 128*136*2*2);            // 2 x [128][40] p tile
    __half* Xx = Xp + 2*128*XP16;                           // 2 x [128][40] x tile
    int t = threadIdx.x;

    for (int idx = t; idx < 128*128; idx += 256) {
        int m = idx >> 7, k = idx & 127;
        w_split(Wout[idx], Wh, Wl, m*136 + k);
    }
    const int NT = NPIXF/32;
    auto load_tile = [&](int buf, int tile) {
        __half* XP = Xp + buf*128*XP16;
        __half* XX = Xx + buf*128*XP16;
        int p0 = tile*32, bb = p0 >> 17, s0 = p0 & (HWF - 1);
        const __half* pb = g_p16 + (size_t)bb*128*HWF + s0;
        const __half* xb = g_x16 + (size_t)bb*128*HWF + s0;
        #pragma unroll
        for (int c8 = 0; c8 < 2; c8++) {
            int chunk = t + 256*c8;
            int r = chunk >> 2, q = chunk & 3;
            cpa16(XP + r*XP16 + q*8, pb + (size_t)r*HWF + q*8);
        }
        #pragma unroll
        for (int c8 = 0; c8 < 2; c8++) {
            int chunk = t + 256*c8;
            int r = chunk >> 2, q = chunk & 3;
            cpa16(XX + r*XP16 + q*8, xb + (size_t)r*HWF + q*8);
        }
    };
    int lane = t & 31, warp = t >> 5;
    int wm = warp >> 1, wn = warp & 1;
    int m0 = wm*32, n0 = wn*16;
    int r0 = m0 + (lane >> 2);
    int pcb = n0 + 2*(lane & 3);

    int tile = blockIdx.x, par = 0;
    if (tile < NT) load_tile(0, tile);
    CPA_COMMIT();
    __syncthreads();
    for (; tile < NT; tile += GRD) {
        int nxt = tile + GRD;
        if (nxt < NT) load_tile(par ^ 1, nxt);
        CPA_COMMIT();
        CPA_WAIT1();
        __syncthreads();

        // init C from the staged p16 tile (fragment positions)
        const __half* P = Xp + par*128*XP16;
        float C[2][2][4];
        #pragma unroll
        for (int i = 0; i < 2; i++) {
            int r = r0 + i*16;
            #pragma unroll
            for (int j = 0; j < 2; j++) {
                int pc = pcb + j*8;
                C[i][j][0] = __half2float(P[r*XP16 + pc]);
                C[i][j][1] = __half2float(P[r*XP16 + pc + 1]);
                C[i][j][2] = __half2float(P[(r + 8)*XP16 + pc]);
                C[i][j][3] = __half2float(P[(r + 8)*XP16 + pc + 1]);
            }
        }
        gemm_ms16<2,2,128,XP16,136>(Wh, Wl, Xx + par*128*XP16, C, m0, n0, lane);

        int p0 = tile*32, bb = p0 >> 17, s0 = p0 & (HWF - 1);
        float* ob = out + (size_t)bb*128*HWF + s0;
        #pragma unroll
        for (int i = 0; i < 2; i++) {
            int r = r0 + i*16;
            #pragma unroll
            for (int j = 0; j < 2; j++) {
                int ccol = pcb + j*8;
                *(float2*)(ob + (size_t)r*HWF + ccol)       = make_float2(C[i][j][0], C[i][j][1]);
                *(float2*)(ob + (size_t)(r + 8)*HWF + ccol) = make_float2(C[i][j][2], C[i][j][3]);
            }
        }
        __syncthreads();
        par ^= 1;
    }
}

extern "C" void kernel_launch(void* const* d_in, const int* in_sizes, int n_in,
                              void* d_out, int out_size) {
    const float* h_prev = (const float*)d_in[0];
    const float* h_init = (const float*)d_in[1];
    const float* Wq   = (const float*)d_in[2];
    const float* bq   = (const float*)d_in[3];
    const float* Wk   = (const float*)d_in[4];
    const float* bk   = (const float*)d_in[5];
    const float* Wvp  = (const float*)d_in[6];
    const float* bvp  = (const float*)d_in[7];
    const float* Wvi  = (const float*)d_in[8];
    const float* bvi  = (const float*)d_in[9];
    const float* Wout = (const float*)d_in[10];
    const float* bout = (const float*)d_in[11];
    float* out = (float*)d_out;

    cudaFuncSetAttribute(k_kv,   cudaFuncAttributeMaxDynamicSharedMemorySize, KV_SMEM);
    cudaFuncSetAttribute(k_qp,   cudaFuncAttributeMaxDynamicSharedMemorySize, QP_SMEM);
    cudaFuncSetAttribute(k_attn, cudaFuncAttributeMaxDynamicSharedMemorySize, ATTN_SMEM);
    cudaFuncSetAttribute(k_out,  cudaFuncAttributeMaxDynamicSharedMemorySize, O_SMEM);

    k_fuse<<<CC, CC>>>(Wout, Wvi, bvi, bout);
    k_kv<<<GRD, 256, KV_SMEM>>>(h_prev, Wk, bk, Wvp, bvp);
    k_qp<<<GRD, 256, QP_SMEM>>>(h_init, Wq, bq);
    dim3 ag(CW2/CTX, CH2/CTY, CB);
    k_attn<<<ag, 256, ATTN_SMEM>>>();
    k_out<<<GRD, 256, O_SMEM>>>(Wout, out);
}

// round 15
// speedup vs baseline: 2.5581x; 1.0393x over previous
#include <cuda_runtime.h>
#include <cuda_fp16.h>
#include <cstdint>

#define CB 2
#define CC 128
#define CCK 64
#define CH 256
#define CW 512
#define CH2 128
#define CW2 256
#define HWF (CH*CW)
#define HW2 (CH2*CW2)
#define NPIXF (CB*HWF)
#define NPIX2 (CB*HW2)
#define GRD 148

#define CTY 4
#define CTX 16
#define HX 18
#define NH 108
#define KPH 72
#define VPH 136
#define AP 13

typedef unsigned long long ull;
typedef unsigned int u32;
typedef unsigned short u16;

__device__ __forceinline__ ull fma2(ull a, ull b, ull c) {
    ull d; asm("fma.rn.f32x2 %0, %1, %2, %3;" : "=l"(d) : "l"(a), "l"(b), "l"(c)); return d;
}
__device__ __forceinline__ ull pk2(float x) {
    ull r; asm("mov.b64 %0, {%1, %1};" : "=l"(r) : "f"(x)); return r;
}
__device__ __forceinline__ ull pk2p(float x, float y) {
    ull r; asm("mov.b64 %0, {%1, %2};" : "=l"(r) : "f"(x), "f"(y)); return r;
}
__device__ __forceinline__ float2 upk(ull v) {
    float2 o; asm("mov.b64 {%0, %1}, %2;" : "=f"(o.x), "=f"(o.y) : "l"(v)); return o;
}
__device__ __forceinline__ ull ld2(const float* p) { return *reinterpret_cast<const ull*>(p); }

__device__ __forceinline__ void ldsm4(u32* r, const __half* p) {
    u32 sa = (u32)__cvta_generic_to_shared(p);
    asm volatile("ldmatrix.sync.aligned.m8n8.x4.shared.b16 {%0,%1,%2,%3}, [%4];"
        : "=r"(r[0]), "=r"(r[1]), "=r"(r[2]), "=r"(r[3]) : "r"(sa));
}
__device__ __forceinline__ void mma16816(float* c, const u32* a, u32 b0, u32 b1) {
    asm volatile("mma.sync.aligned.m16n8k16.row.col.f32.f16.f16.f32 "
        "{%0,%1,%2,%3}, {%4,%5,%6,%7}, {%8,%9}, {%0,%1,%2,%3};"
        : "+f"(c[0]), "+f"(c[1]), "+f"(c[2]), "+f"(c[3])
        : "r"(a[0]), "r"(a[1]), "r"(a[2]), "r"(a[3]), "r"(b0), "r"(b1));
}
__device__ __forceinline__ u32 cvt2(float hiF, float loF) {
    u32 r; asm("cvt.rn.f16x2.f32 %0, %1, %2;" : "=r"(r) : "f"(hiF), "f"(loF)); return r;
}
__device__ __forceinline__ void cpa16(void* dst, const void* src) {
    u32 d = (u32)__cvta_generic_to_shared(dst);
    asm volatile("cp.async.cg.shared.global [%0], [%1], 16;" :: "r"(d), "l"(src));
}
#define CPA_COMMIT() asm volatile("cp.async.commit_group;")
#define CPA_WAIT1()  asm volatile("cp.async.wait_group 1;")

__device__ __half g_k16[(size_t)NPIX2*CCK];
__device__ __half g_v16[(size_t)NPIX2*CC];
__device__ __half g_q16[(size_t)NPIXF*CCK];
__device__ __half g_p16[(size_t)NPIXF*CC];   // partial = Wc@h + beff, NCHW fp16
__device__ __half g_x16[(size_t)NPIXF*CC];   // NCHW fp16
__device__ float  g_Wc[CC*CC];
__device__ float  g_beff[CC];

__global__ void k_fuse(const float* __restrict__ Wout, const float* __restrict__ Wvi,
                       const float* __restrict__ bvi, const float* __restrict__ bout) {
    int o = blockIdx.x, i = threadIdx.x;
    float acc = 0.f;
    for (int m = 0; m < CC; m++) acc += Wout[o*CC + m] * Wvi[m*CC + i];
    g_Wc[o*CC + i] = acc;
    if (i == 0) {
        float b = bout[o];
        for (int m = 0; m < CC; m++) b += Wout[o*CC + m] * bvi[m];
        g_beff[o] = b;
    }
}

// fp16 2-product GEMM mainloop: W split (hi+lo fp16), X fp32 smem -> fp16 frag.
template<int MF, int NF, int KT, int XP, int KPW>
__device__ __forceinline__ void gemm_ms(const __half* __restrict__ Wh,
                                        const __half* __restrict__ Wl,
                                        const float* __restrict__ Xs,
                                        float C[MF][NF][4], int m0, int n0, int lane) {
    const int lrow = (lane & 7) + ((lane >> 3) & 1) * 8;
    const int lk8  = ((lane >> 4) & 1) * 8;
    const int bn   = n0 + (lane >> 2);
    const int bk   = 2 * (lane & 3);
    for (int ks = 0; ks < KT/16; ks++) {
        u32 ah[MF][4], al[MF][4];
        #pragma unroll
        for (int i = 0; i < MF; i++) {
            int off = (m0 + i*16 + lrow)*KPW + ks*16 + lk8;
            ldsm4(ah[i], Wh + off);
            ldsm4(al[i], Wl + off);
        }
        u32 bh[NF][2];
        #pragma unroll
        for (int j = 0; j < NF; j++) {
            const float* xp = Xs + (ks*16 + bk)*XP + bn + j*8;
            float x0 = xp[0], x1 = xp[XP], x2 = xp[8*XP], x3 = xp[9*XP];
            bh[j][0] = cvt2(x1, x0);
            bh[j][1] = cvt2(x3, x2);
        }
        #pragma unroll
        for (int i = 0; i < MF; i++)
            #pragma unroll
            for (int j = 0; j < NF; j++) mma16816(C[i][j], ah[i], bh[j][0], bh[j][1]);
        #pragma unroll
        for (int i = 0; i < MF; i++)
            #pragma unroll
            for (int j = 0; j < NF; j++) mma16816(C[i][j], al[i], bh[j][0], bh[j][1]);
    }
}

// Variant: X already fp16 in smem.
template<int MF, int NF, int KT, int XP, int KPW>
__device__ __forceinline__ void gemm_ms16(const __half* __restrict__ Wh,
                                          const __half* __restrict__ Wl,
                                          const __half* __restrict__ Xs,
                                          float C[MF][NF][4], int m0, int n0, int lane) {
    const int lrow = (lane & 7) + ((lane >> 3) & 1) * 8;
    const int lk8  = ((lane >> 4) & 1) * 8;
    const int bn   = n0 + (lane >> 2);
    const int bk   = 2 * (lane & 3);
    for (int ks = 0; ks < KT/16; ks++) {
        u32 ah[MF][4], al[MF][4];
        #pragma unroll
        for (int i = 0; i < MF; i++) {
            int off = (m0 + i*16 + lrow)*KPW + ks*16 + lk8;
            ldsm4(ah[i], Wh + off);
            ldsm4(al[i], Wl + off);
        }
        u32 bh[NF][2];
        #pragma unroll
        for (int j = 0; j < NF; j++) {
            const __half* xp = Xs + (ks*16 + bk)*XP + bn + j*8;
            u16 x0 = __half_as_ushort(xp[0]),    x1 = __half_as_ushort(xp[XP]);
            u16 x2 = __half_as_ushort(xp[8*XP]), x3 = __half_as_ushort(xp[9*XP]);
            bh[j][0] = ((u32)x1 << 16) | x0;
            bh[j][1] = ((u32)x3 << 16) | x2;
        }
        #pragma unroll
        for (int i = 0; i < MF; i++)
            #pragma unroll
            for (int j = 0; j < NF; j++) mma16816(C[i][j], ah[i], bh[j][0], bh[j][1]);
        #pragma unroll
        for (int i = 0; i < MF; i++)
            #pragma unroll
            for (int j = 0; j < NF; j++) mma16816(C[i][j], al[i], bh[j][0], bh[j][1]);
    }
}

__device__ __forceinline__ void w_split(float w, __half* Wh, __half* Wl, int off) {
    __half h = __float2half_rn(w);
    Wh[off] = h;
    Wl[off] = __float2half_rn(w - __half2float(h));
}

// K1: coarse k,v. M=192, K=128, BN=32. 2-stage cp.async. fp16 outputs.
#define KV_SMEM (192*136*2*2 + 2*128*36*4 + 32*196*4)
__global__ void __launch_bounds__(256) k_kv(const float* __restrict__ hp,
        const float* __restrict__ Wk, const float* __restrict__ bk,
        const float* __restrict__ Wvp, const float* __restrict__ bvp) {
    extern __shared__ char smraw[];
    __half* Wh = (__half*)smraw;
    __half* Wl = Wh + 192*136;
    float* Xs = (float*)(smraw + 192*136*2*2);
    float* Ss = Xs + 2*128*36;
    int t = threadIdx.x;

    for (int idx = t; idx < 192*128; idx += 256) {
        int m = idx >> 7, k = idx & 127;
        float w = (m < 64) ? Wk[m*128 + k] : Wvp[(m - 64)*128 + k];
        w_split(w, Wh, Wl, m*136 + k);
    }
    const int NT = NPIX2/32;
    auto load_tile = [&](int buf, int tile) {
        float* X = Xs + buf*128*36;
        int p0 = tile*32, bb = p0 >> 15, s0 = p0 & (HW2 - 1);
        const float* hb = hp + (size_t)bb*128*HW2 + s0;
        #pragma unroll
        for (int c8 = 0; c8 < 4; c8++) {
            int chunk = t + 256*c8;
            int r = chunk >> 3, q = chunk & 7;
            cpa16(X + r*36 + q*4, hb + (size_t)r*HW2 + q*4);
        }
    };
    int lane = t & 31, warp = t >> 5;
    int wm = warp >> 1, wn = warp & 1;
    int m0 = wm*48, n0 = wn*16;
    int r0 = m0 + (lane >> 2);

    int tile = blockIdx.x, par = 0;
    if (tile < NT) load_tile(0, tile);
    CPA_COMMIT();
    __syncthreads();
    for (; tile < NT; tile += GRD) {
        int nxt = tile + GRD;
        if (nxt < NT) load_tile(par ^ 1, nxt);
        CPA_COMMIT();
        CPA_WAIT1();
        __syncthreads();

        float C[3][2][4];
        #pragma unroll
        for (int i = 0; i < 3; i++) {
            int ra = r0 + i*16, rb = ra + 8;
            float b0 = (ra < 64) ? bk[ra] : bvp[ra - 64];
            float b1 = (rb < 64) ? bk[rb] : bvp[rb - 64];
            #pragma unroll
            for (int j = 0; j < 2; j++) {
                C[i][j][0] = C[i][j][1] = b0;
                C[i][j][2] = C[i][j][3] = b1;
            }
        }
        gemm_ms<3,2,128,36,136>(Wh, Wl, Xs + par*128*36, C, m0, n0, lane);
        __syncthreads();
        #pragma unroll
        for (int i = 0; i < 3; i++)
            #pragma unroll
            for (int j = 0; j < 2; j++) {
                int pc = n0 + j*8 + 2*(lane & 3);
                int rr = m0 + i*16 + (lane >> 2);
                Ss[pc*196 + rr]           = C[i][j][0];
                Ss[(pc + 1)*196 + rr]     = C[i][j][1];
                Ss[pc*196 + rr + 8]       = C[i][j][2];
                Ss[(pc + 1)*196 + rr + 8] = C[i][j][3];
            }
        __syncthreads();
        int p0 = tile*32;
        #pragma unroll
        for (int c = 0; c < 2; c++) {
            int idx = t + 256*c;
            int p = idx >> 4, f4 = idx & 15;
            float4 v = *(const float4*)(Ss + p*196 + f4*4);
            u32 h0 = cvt2(v.y, v.x), h1 = cvt2(v.w, v.z);
            *(uint2*)(g_k16 + (size_t)(p0 + p)*64 + f4*4) = make_uint2(h0, h1);
        }
        #pragma unroll
        for (int c = 0; c < 4; c++) {
            int idx = t + 256*c;
            int p = idx >> 5, f5 = idx & 31;
            float4 v = *(const float4*)(Ss + p*196 + 64 + f5*4);
            u32 h0 = cvt2(v.y, v.x), h1 = cvt2(v.w, v.z);
            *(uint2*)(g_v16 + (size_t)(p0 + p)*128 + f5*4) = make_uint2(h0, h1);
        }
        __syncthreads();
        par ^= 1;
    }
}

// K2: merged q + partial: [Wc(128); Wq(64)] @ h_init. M=192, K=128, BN=64.
#define QP_SMEM (192*136*2*2 + 2*128*68*4 + 64*68*4)
__global__ void __launch_bounds__(256) k_qp(const float* __restrict__ hi,
        const float* __restrict__ Wq, const float* __restrict__ bq) {
    extern __shared__ char smraw[];
    __half* Wh = (__half*)smraw;
    __half* Wl = Wh + 192*136;
    float* Xs = (float*)(smraw + 192*136*2*2);
    float* Ss = Xs + 2*128*68;
    int t = threadIdx.x;

    for (int idx = t; idx < 192*128; idx += 256) {
        int m = idx >> 7, k = idx & 127;
        float w = (m < 128) ? g_Wc[m*128 + k] : Wq[(m - 128)*128 + k];
        w_split(w, Wh, Wl, m*136 + k);
    }
    const int NT = NPIXF/64;
    auto load_tile = [&](int buf, int tile) {
        float* X = Xs + buf*128*68;
        int p0 = tile*64, bb = p0 >> 17, s0 = p0 & (HWF - 1);
        const float* hb = hi + (size_t)bb*128*HWF + s0;
        #pragma unroll
        for (int c8 = 0; c8 < 8; c8++) {
            int chunk = t + 256*c8;
            int r = chunk >> 4, q = chunk & 15;
            cpa16(X + r*68 + q*4, hb + (size_t)r*HWF + q*4);
        }
    };
    int lane = t & 31, warp = t >> 5;
    int wm = warp >> 1, wn = warp & 1;
    int m0 = wm*48, n0 = wn*32;
    int r0 = m0 + (lane >> 2);

    int tile = blockIdx.x, par = 0;
    if (tile < NT) load_tile(0, tile);
    CPA_COMMIT();
    __syncthreads();
    for (; tile < NT; tile += GRD) {
        int nxt = tile + GRD;
        if (nxt < NT) load_tile(par ^ 1, nxt);
        CPA_COMMIT();
        CPA_WAIT1();
        __syncthreads();

        float C[3][4][4];
        #pragma unroll
        for (int i = 0; i < 3; i++) {
            int ra = r0 + i*16, rb = ra + 8;
            float b0 = (ra < 128) ? g_beff[ra] : bq[ra - 128];
            float b1 = (rb < 128) ? g_beff[rb] : bq[rb - 128];
            #pragma unroll
            for (int j = 0; j < 4; j++) {
                C[i][j][0] = C[i][j][1] = b0;
                C[i][j][2] = C[i][j][3] = b1;
            }
        }
        gemm_ms<3,4,128,68,136>(Wh, Wl, Xs + par*128*68, C, m0, n0, lane);

        int p0 = tile*64, bb = p0 >> 17, s0 = p0 & (HWF - 1);
        __half* pb = g_p16 + (size_t)bb*128*HWF + s0;
        #pragma unroll
        for (int i = 0; i < 3; i++) {
            int row16 = m0 + i*16;
            int rr = row16 + (lane >> 2);
            int pcb = n0 + 2*(lane & 3);
            if (row16 < 128) {
                #pragma unroll
                for (int j = 0; j < 4; j++) {
                    int pc = pcb + j*8;
                    *(u32*)(pb + (size_t)rr*HWF + pc)       = cvt2(C[i][j][1], C[i][j][0]);
                    *(u32*)(pb + (size_t)(rr + 8)*HWF + pc) = cvt2(C[i][j][3], C[i][j][2]);
                }
            } else {
                int rq = rr - 128;
                #pragma unroll
                for (int j = 0; j < 4; j++) {
                    int pc = pcb + j*8;
                    Ss[pc*68 + rq]           = C[i][j][0];
                    Ss[(pc + 1)*68 + rq]     = C[i][j][1];
                    Ss[pc*68 + rq + 8]       = C[i][j][2];
                    Ss[(pc + 1)*68 + rq + 8] = C[i][j][3];
                }
            }
        }
        __syncthreads();
        #pragma unroll
        for (int c = 0; c < 4; c++) {
            int idx = t + 256*c;
            int p = idx >> 4, f4 = idx & 15;
            float4 v = *(const float4*)(Ss + p*68 + f4*4);
            u32 h0 = cvt2(v.y, v.x), h1 = cvt2(v.w, v.z);
            *(uint2*)(g_q16 + (size_t)(p0 + p)*64 + f4*4) = make_uint2(h0, h1);
        }
        __syncthreads();
        par ^= 1;
    }
}

// K3: attention. fp16 k/v smem (3 blocks/SM), fp16 q/x gmem.
#define ATTN_SMEM (NH*KPH*2 + NH*VPH*2 + 256*AP*4)
__global__ void __launch_bounds__(256) k_attn() {
    extern __shared__ char smraw[];
    __half* ks = (__half*)smraw;
    __half* vs = ks + NH*KPH;
    float* as = (float*)(smraw + NH*KPH*2 + NH*VPH*2);
    int t = threadIdx.x;
    int b = blockIdx.z;
    int cy0 = blockIdx.y * CTY, cx0 = blockIdx.x * CTX;
    int fy0 = cy0*2, fx0 = cx0*2;

    for (int idx = t; idx < NH*8; idx += 256) {
        int pix = idx >> 3, c8 = idx & 7;
        int hy = pix / HX, hx = pix % HX;
        int gy = cy0 + hy - 1, gx = cx0 + hx - 1;
        uint4 v = make_uint4(0u, 0u, 0u, 0u);
        if ((unsigned)gy < CH2 && (unsigned)gx < CW2)
            v = *(const uint4*)(g_k16 + ((size_t)(b*HW2 + gy*CW2 + gx))*CCK + c8*8);
        *(uint4*)(ks + pix*KPH + c8*8) = v;
    }
    for (int idx = t; idx < NH*16; idx += 256) {
        int pix = idx >> 4, c8 = idx & 15;
        int hy = pix / HX, hx = pix % HX;
        int gy = cy0 + hy - 1, gx = cx0 + hx - 1;
        uint4 v = make_uint4(0u, 0u, 0u, 0u);
        if ((unsigned)gy < CH2 && (unsigned)gx < CW2)
            v = *(const uint4*)(g_v16 + ((size_t)(b*HW2 + gy*CW2 + gx))*CC + c8*8);
        *(uint4*)(vs + pix*VPH + c8*8) = v;
    }
    __syncthreads();

    {   // Phase A
        int p = t;
        int fy = p >> 5, fx = p & 31;
        int cy = fy >> 1, cx = fx >> 1;
        const uint4* gq = reinterpret_cast<const uint4*>(
            g_q16 + ((size_t)((b*CH + fy0 + fy)*CW + fx0 + fx))*CCK);
        const __half* kb = ks + (cy*HX + cx)*KPH;
        ull sc2[9];
        #pragma unroll
        for (int j = 0; j < 9; j++) sc2[j] = 0ull;
        #pragma unroll 2
        for (int cc = 0; cc < 8; cc++) {
            uint4 qv = gq[cc];
            float2 f0 = __half22float2(*reinterpret_cast<__half2*>(&qv.x));
            float2 f1 = __half22float2(*reinterpret_cast<__half2*>(&qv.y));
            float2 f2 = __half22float2(*reinterpret_cast<__half2*>(&qv.z));
            float2 f3 = __half22float2(*reinterpret_cast<__half2*>(&qv.w));
            ull q0 = pk2p(f0.x, f0.y), q1 = pk2p(f1.x, f1.y);
            ull q2 = pk2p(f2.x, f2.y), q3 = pk2p(f3.x, f3.y);
            int c = cc*8;
            #pragma unroll
            for (int dy = 0; dy < 3; dy++)
                #pragma unroll
                for (int dx = 0; dx < 3; dx++) {
                    int j = dy*3 + dx;
                    uint4 kv4 = *(const uint4*)(kb + (dy*HX + dx)*KPH + c);
                    float2 g0 = __half22float2(*reinterpret_cast<__half2*>(&kv4.x));
                    float2 g1 = __half22float2(*reinterpret_cast<__half2*>(&kv4.y));
                    float2 g2 = __half22float2(*reinterpret_cast<__half2*>(&kv4.z));
                    float2 g3 = __half22float2(*reinterpret_cast<__half2*>(&kv4.w));
                    sc2[j] = fma2(q0, pk2p(g0.x, g0.y), sc2[j]);
                    sc2[j] = fma2(q1, pk2p(g1.x, g1.y), sc2[j]);
                    sc2[j] = fma2(q2, pk2p(g2.x, g2.y), sc2[j]);
                    sc2[j] = fma2(q3, pk2p(g3.x, g3.y), sc2[j]);
                }
        }
        float sc[9];
        #pragma unroll
        for (int j = 0; j < 9; j++) { float2 v = upk(sc2[j]); sc[j] = v.x + v.y; }
        float m = sc[0];
        #pragma unroll
        for (int j = 1; j < 9; j++) m = fmaxf(m, sc[j]);
        float s = 0.f;
        #pragma unroll
        for (int j = 0; j < 9; j++) { sc[j] = __expf(sc[j] - m); s += sc[j]; }
        float inv = 1.f / s;
        #pragma unroll
        for (int j = 0; j < 9; j++) as[p*AP + j] = sc[j]*inv;
    }
    __syncthreads();

    {   // Phase B: fp16 v loads (uint2 = 4 ch)
        int cell = t & 63, cg = t >> 6;
        int cyl = cell >> 4, cxl = cell & 15;
        ull a01[9], a23[9];
        int p00 = (2*cyl)*32 + 2*cxl;
        int p10 = p00 + 32;
        #pragma unroll
        for (int j = 0; j < 9; j++) {
            a01[j] = pk2p(as[p00*AP + j], as[(p00 + 1)*AP + j]);
            a23[j] = pk2p(as[p10*AP + j], as[(p10 + 1)*AP + j]);
        }
        const __half* vb = vs + (cyl*HX + cxl)*VPH + cg*32;
        size_t obase = ((size_t)(b*CC + cg*32))*HWF
                     + (size_t)(fy0 + 2*cyl)*CW + fx0 + 2*cxl;
        #pragma unroll 2
        for (int c4 = 0; c4 < 8; c4++) {
            ull o01[4] = {0ull, 0ull, 0ull, 0ull};
            ull o23[4] = {0ull, 0ull, 0ull, 0ull};
            #pragma unroll
            for (int dy = 0; dy < 3; dy++)
                #pragma unroll
                for (int dx = 0; dx < 3; dx++) {
                    int j = dy*3 + dx;
                    uint2 vv2 = *(const uint2*)(vb + (dy*HX + dx)*VPH + c4*4);
                    float2 g0 = __half22float2(*reinterpret_cast<__half2*>(&vv2.x));
                    float2 g1 = __half22float2(*reinterpret_cast<__half2*>(&vv2.y));
                    o01[0] = fma2(a01[j], pk2(g0.x), o01[0]);
                    o01[1] = fma2(a01[j], pk2(g0.y), o01[1]);
                    o01[2] = fma2(a01[j], pk2(g1.x), o01[2]);
                    o01[3] = fma2(a01[j], pk2(g1.y), o01[3]);
                    o23[0] = fma2(a23[j], pk2(g0.x), o23[0]);
                    o23[1] = fma2(a23[j], pk2(g0.y), o23[1]);
                    o23[2] = fma2(a23[j], pk2(g1.x), o23[2]);
                    o23[3] = fma2(a23[j], pk2(g1.y), o23[3]);
                }
            #pragma unroll
            for (int e = 0; e < 4; e++) {
                float2 r01 = upk(o01[e]), r23 = upk(o23[e]);
                size_t oa = obase + (size_t)(c4*4 + e)*HWF;
                *reinterpret_cast<u32*>(g_x16 + oa)      = cvt2(r01.y, r01.x);
                *reinterpret_cast<u32*>(g_x16 + oa + CW) = cvt2(r23.y, r23.x);
            }
        }
    }
}

// K4: out = p + Wout@x. M=128, K=128, BN=64. fp16 staging, MF=2 NF=4.
#define XOP 72
#define O_SMEM (128*136*2*2 + 4*128*XOP*2)
__global__ void __launch_bounds__(256) k_out(const float* __restrict__ Wout,
        float* __restrict__ out) {
    extern __shared__ char smraw[];
    __half* Wh = (__half*)smraw;
    __half* Wl = Wh + 128*136;
    __half* Xp = (__half*)(smraw + 128*136*2*2);            // 2 x [128][72]
    __half* Xx = Xp + 2*128*XOP;                            // 2 x [128][72]
    int t = threadIdx.x;

    for (int idx = t; idx < 128*128; idx += 256) {
        int m = idx >> 7, k = idx & 127;
        w_split(Wout[idx], Wh, Wl, m*136 + k);
    }
    const int NT = NPIXF/64;
    auto load_tile = [&](int buf, int tile) {
        __half* XP = Xp + buf*128*XOP;
        __half* XX = Xx + buf*128*XOP;
        int p0 = tile*64, bb = p0 >> 17, s0 = p0 & (HWF - 1);
        const __half* pb = g_p16 + (size_t)bb*128*HWF + s0;
        const __half* xb = g_x16 + (size_t)bb*128*HWF + s0;
        #pragma unroll
        for (int c8 = 0; c8 < 4; c8++) {
            int chunk = t + 256*c8;
            int r = chunk >> 3, q = chunk & 7;
            cpa16(XP + r*XOP + q*8, pb + (size_t)r*HWF + q*8);
        }
        #pragma unroll
        for (int c8 = 0; c8 < 4; c8++) {
            int chunk = t + 256*c8;
            int r = chunk >> 3, q = chunk & 7;
            cpa16(XX + r*XOP + q*8, xb + (size_t)r*HWF + q*8);
        }
    };
    int lane = t & 31, warp = t >> 5;
    int wm = warp >> 1, wn = warp & 1;
    int m0 = wm*32, n0 = wn*32;
    int r0 = m0 + (lane >> 2);
    int pcb = n0 + 2*(lane & 3);

    int tile = blockIdx.x, par = 0;
    if (tile < NT) load_tile(0, tile);
    CPA_COMMIT();
    __syncthreads();
    for (; tile < NT; tile += GRD) {
        int nxt = tile + GRD;
        if (nxt < NT) load_tile(par ^ 1, nxt);
        CPA_COMMIT();
        CPA_WAIT1();
        __syncthreads();

        const __half* P = Xp + par*128*XOP;
        float C[2][4][4];
        #pragma unroll
        for (int i = 0; i < 2; i++) {
            int r = r0 + i*16;
            #pragma unroll
            for (int j = 0; j < 4; j++) {
                int pc = pcb + j*8;
                C[i][j][0] = __half2float(P[r*XOP + pc]);
                C[i][j][1] = __half2float(P[r*XOP + pc + 1]);
                C[i][j][2] = __half2float(P[(r + 8)*XOP + pc]);
                C[i][j][3] = __half2float(P[(r + 8)*XOP + pc + 1]);
            }
        }
        gemm_ms16<2,4,128,XOP,136>(Wh, Wl, Xx + par*128*XOP, C, m0, n0, lane);

        int p0 = tile*64, bb = p0 >> 17, s0 = p0 & (HWF - 1);
        float* ob = out + (size_t)bb*128*HWF + s0;
        #pragma unroll
        for (int i = 0; i < 2; i++) {
            int r = r0 + i*16;
            #pragma unroll
            for (int j = 0; j < 4; j++) {
                int ccol = pcb + j*8;
                *(float2*)(ob + (size_t)r*HWF + ccol)       = make_float2(C[i][j][0], C[i][j][1]);
                *(float2*)(ob + (size_t)(r + 8)*HWF + ccol) = make_float2(C[i][j][2], C[i][j][3]);
            }
        }
        __syncthreads();
        par ^= 1;
    }
}

extern "C" void kernel_launch(void* const* d_in, const int* in_sizes, int n_in,
                              void* d_out, int out_size) {
    const float* h_prev = (const float*)d_in[0];
    const float* h_init = (const float*)d_in[1];
    const float* Wq   = (const float*)d_in[2];
    const float* bq   = (const float*)d_in[3];
    const float* Wk   = (const float*)d_in[4];
    const float* bk   = (const float*)d_in[5];
    const float* Wvp  = (const float*)d_in[6];
    const float* bvp  = (const float*)d_in[7];
    const float* Wvi  = (const float*)d_in[8];
    const float* bvi  = (const float*)d_in[9];
    const float* Wout = (const float*)d_in[10];
    const float* bout = (const float*)d_in[11];
    float* out = (float*)d_out;

    cudaFuncSetAttribute(k_kv,   cudaFuncAttributeMaxDynamicSharedMemorySize, KV_SMEM);
    cudaFuncSetAttribute(k_qp,   cudaFuncAttributeMaxDynamicSharedMemorySize, QP_SMEM);
    cudaFuncSetAttribute(k_attn, cudaFuncAttributeMaxDynamicSharedMemorySize, ATTN_SMEM);
    cudaFuncSetAttribute(k_out,  cudaFuncAttributeMaxDynamicSharedMemorySize, O_SMEM);

    k_fuse<<<CC, CC>>>(Wout, Wvi, bvi, bout);
    k_kv<<<GRD, 256, KV_SMEM>>>(h_prev, Wk, bk, Wvp, bvp);
    k_qp<<<GRD, 256, QP_SMEM>>>(h_init, Wq, bq);
    dim3 ag(CW2/CTX, CH2/CTY, CB);
    k_attn<<<ag, 256, ATTN_SMEM>>>();
    k_out<<<GRD, 256, O_SMEM>>>(Wout, out);
}

// round 16
// speedup vs baseline: 2.6594x; 1.0396x over previous
#include <cuda_runtime.h>
#include <cuda_fp16.h>
#include <cstdint>

#define CB 2
#define CC 128
#define CCK 64
#define CH 256
#define CW 512
#define CH2 128
#define CW2 256
#define HWF (CH*CW)
#define HW2 (CH2*CW2)
#define NPIXF (CB*HWF)
#define NPIX2 (CB*HW2)
#define GRD 148

#define CTY 4
#define CTX 16
#define HX 18
#define NH 108
#define KPH 72
#define VPH 136
#define AP 13

typedef unsigned long long ull;
typedef unsigned int u32;
typedef unsigned short u16;

__device__ __forceinline__ ull fma2(ull a, ull b, ull c) {
    ull d; asm("fma.rn.f32x2 %0, %1, %2, %3;" : "=l"(d) : "l"(a), "l"(b), "l"(c)); return d;
}
__device__ __forceinline__ ull pk2(float x) {
    ull r; asm("mov.b64 %0, {%1, %1};" : "=l"(r) : "f"(x)); return r;
}
__device__ __forceinline__ ull pk2p(float x, float y) {
    ull r; asm("mov.b64 %0, {%1, %2};" : "=l"(r) : "f"(x), "f"(y)); return r;
}
__device__ __forceinline__ float2 upk(ull v) {
    float2 o; asm("mov.b64 {%0, %1}, %2;" : "=f"(o.x), "=f"(o.y) : "l"(v)); return o;
}

__device__ __forceinline__ void ldsm4(u32* r, const __half* p) {
    u32 sa = (u32)__cvta_generic_to_shared(p);
    asm volatile("ldmatrix.sync.aligned.m8n8.x4.shared.b16 {%0,%1,%2,%3}, [%4];"
        : "=r"(r[0]), "=r"(r[1]), "=r"(r[2]), "=r"(r[3]) : "r"(sa));
}
__device__ __forceinline__ void mma16816(float* c, const u32* a, u32 b0, u32 b1) {
    asm volatile("mma.sync.aligned.m16n8k16.row.col.f32.f16.f16.f32 "
        "{%0,%1,%2,%3}, {%4,%5,%6,%7}, {%8,%9}, {%0,%1,%2,%3};"
        : "+f"(c[0]), "+f"(c[1]), "+f"(c[2]), "+f"(c[3])
        : "r"(a[0]), "r"(a[1]), "r"(a[2]), "r"(a[3]), "r"(b0), "r"(b1));
}
__device__ __forceinline__ u32 cvt2(float hiF, float loF) {
    u32 r; asm("cvt.rn.f16x2.f32 %0, %1, %2;" : "=r"(r) : "f"(hiF), "f"(loF)); return r;
}
__device__ __forceinline__ void cpa16(void* dst, const void* src) {
    u32 d = (u32)__cvta_generic_to_shared(dst);
    asm volatile("cp.async.cg.shared.global [%0], [%1], 16;" :: "r"(d), "l"(src));
}
#define CPA_COMMIT() asm volatile("cp.async.commit_group;")
#define CPA_WAIT1()  asm volatile("cp.async.wait_group 1;")

__device__ __half g_k16[(size_t)NPIX2*CCK];
__device__ __half g_v16[(size_t)NPIX2*CC];
__device__ __half g_q16[(size_t)NPIXF*CCK];
__device__ __half g_p16[(size_t)NPIXF*CC];   // partial = Wc@h + beff, NCHW fp16
__device__ __half g_x16[(size_t)NPIXF*CC];   // NCHW fp16
__device__ float  g_Wc[CC*CC];
__device__ float  g_beff[CC];

__global__ void k_fuse(const float* __restrict__ Wout, const float* __restrict__ Wvi,
                       const float* __restrict__ bvi, const float* __restrict__ bout) {
    int o = blockIdx.x, i = threadIdx.x;
    float acc = 0.f;
    for (int m = 0; m < CC; m++) acc += Wout[o*CC + m] * Wvi[m*CC + i];
    g_Wc[o*CC + i] = acc;
    if (i == 0) {
        float b = bout[o];
        for (int m = 0; m < CC; m++) b += Wout[o*CC + m] * bvi[m];
        g_beff[o] = b;
    }
}

// fp16 2-product GEMM mainloop: W split (hi+lo fp16), X fp32 smem -> fp16 frag.
template<int MF, int NF, int KT, int XP, int KPW>
__device__ __forceinline__ void gemm_ms(const __half* __restrict__ Wh,
                                        const __half* __restrict__ Wl,
                                        const float* __restrict__ Xs,
                                        float C[MF][NF][4], int m0, int n0, int lane) {
    const int lrow = (lane & 7) + ((lane >> 3) & 1) * 8;
    const int lk8  = ((lane >> 4) & 1) * 8;
    const int bn   = n0 + (lane >> 2);
    const int bk   = 2 * (lane & 3);
    for (int ks = 0; ks < KT/16; ks++) {
        u32 ah[MF][4], al[MF][4];
        #pragma unroll
        for (int i = 0; i < MF; i++) {
            int off = (m0 + i*16 + lrow)*KPW + ks*16 + lk8;
            ldsm4(ah[i], Wh + off);
            ldsm4(al[i], Wl + off);
        }
        u32 bh[NF][2];
        #pragma unroll
        for (int j = 0; j < NF; j++) {
            const float* xp = Xs + (ks*16 + bk)*XP + bn + j*8;
            float x0 = xp[0], x1 = xp[XP], x2 = xp[8*XP], x3 = xp[9*XP];
            bh[j][0] = cvt2(x1, x0);
            bh[j][1] = cvt2(x3, x2);
        }
        #pragma unroll
        for (int i = 0; i < MF; i++)
            #pragma unroll
            for (int j = 0; j < NF; j++) mma16816(C[i][j], ah[i], bh[j][0], bh[j][1]);
        #pragma unroll
        for (int i = 0; i < MF; i++)
            #pragma unroll
            for (int j = 0; j < NF; j++) mma16816(C[i][j], al[i], bh[j][0], bh[j][1]);
    }
}

// Variant: X already fp16 in smem.
template<int MF, int NF, int KT, int XP, int KPW>
__device__ __forceinline__ void gemm_ms16(const __half* __restrict__ Wh,
                                          const __half* __restrict__ Wl,
                                          const __half* __restrict__ Xs,
                                          float C[MF][NF][4], int m0, int n0, int lane) {
    const int lrow = (lane & 7) + ((lane >> 3) & 1) * 8;
    const int lk8  = ((lane >> 4) & 1) * 8;
    const int bn   = n0 + (lane >> 2);
    const int bk   = 2 * (lane & 3);
    for (int ks = 0; ks < KT/16; ks++) {
        u32 ah[MF][4], al[MF][4];
        #pragma unroll
        for (int i = 0; i < MF; i++) {
            int off = (m0 + i*16 + lrow)*KPW + ks*16 + lk8;
            ldsm4(ah[i], Wh + off);
            ldsm4(al[i], Wl + off);
        }
        u32 bh[NF][2];
        #pragma unroll
        for (int j = 0; j < NF; j++) {
            const __half* xp = Xs + (ks*16 + bk)*XP + bn + j*8;
            u16 x0 = __half_as_ushort(xp[0]),    x1 = __half_as_ushort(xp[XP]);
            u16 x2 = __half_as_ushort(xp[8*XP]), x3 = __half_as_ushort(xp[9*XP]);
            bh[j][0] = ((u32)x1 << 16) | x0;
            bh[j][1] = ((u32)x3 << 16) | x2;
        }
        #pragma unroll
        for (int i = 0; i < MF; i++)
            #pragma unroll
            for (int j = 0; j < NF; j++) mma16816(C[i][j], ah[i], bh[j][0], bh[j][1]);
        #pragma unroll
        for (int i = 0; i < MF; i++)
            #pragma unroll
            for (int j = 0; j < NF; j++) mma16816(C[i][j], al[i], bh[j][0], bh[j][1]);
    }
}

__device__ __forceinline__ void w_split(float w, __half* Wh, __half* Wl, int off) {
    __half h = __float2half_rn(w);
    Wh[off] = h;
    Wl[off] = __float2half_rn(w - __half2float(h));
}

// K1: coarse k,v. M=192, K=128, BN=32. 2-stage cp.async. fp16 outputs.
#define KV_SMEM (192*136*2*2 + 2*128*36*4 + 32*196*4)
__global__ void __launch_bounds__(256) k_kv(const float* __restrict__ hp,
        const float* __restrict__ Wk, const float* __restrict__ bk,
        const float* __restrict__ Wvp, const float* __restrict__ bvp) {
    extern __shared__ char smraw[];
    __half* Wh = (__half*)smraw;
    __half* Wl = Wh + 192*136;
    float* Xs = (float*)(smraw + 192*136*2*2);
    float* Ss = Xs + 2*128*36;
    int t = threadIdx.x;

    for (int idx = t; idx < 192*128; idx += 256) {
        int m = idx >> 7, k = idx & 127;
        float w = (m < 64) ? Wk[m*128 + k] : Wvp[(m - 64)*128 + k];
        w_split(w, Wh, Wl, m*136 + k);
    }
    const int NT = NPIX2/32;
    auto load_tile = [&](int buf, int tile) {
        float* X = Xs + buf*128*36;
        int p0 = tile*32, bb = p0 >> 15, s0 = p0 & (HW2 - 1);
        const float* hb = hp + (size_t)bb*128*HW2 + s0;
        #pragma unroll
        for (int c8 = 0; c8 < 4; c8++) {
            int chunk = t + 256*c8;
            int r = chunk >> 3, q = chunk & 7;
            cpa16(X + r*36 + q*4, hb + (size_t)r*HW2 + q*4);
        }
    };
    int lane = t & 31, warp = t >> 5;
    int wm = warp >> 1, wn = warp & 1;
    int m0 = wm*48, n0 = wn*16;
    int r0 = m0 + (lane >> 2);

    int tile = blockIdx.x, par = 0;
    if (tile < NT) load_tile(0, tile);
    CPA_COMMIT();
    __syncthreads();
    for (; tile < NT; tile += GRD) {
        int nxt = tile + GRD;
        if (nxt < NT) load_tile(par ^ 1, nxt);
        CPA_COMMIT();
        CPA_WAIT1();
        __syncthreads();

        float C[3][2][4];
        #pragma unroll
        for (int i = 0; i < 3; i++) {
            int ra = r0 + i*16, rb = ra + 8;
            float b0 = (ra < 64) ? bk[ra] : bvp[ra - 64];
            float b1 = (rb < 64) ? bk[rb] : bvp[rb - 64];
            #pragma unroll
            for (int j = 0; j < 2; j++) {
                C[i][j][0] = C[i][j][1] = b0;
                C[i][j][2] = C[i][j][3] = b1;
            }
        }
        gemm_ms<3,2,128,36,136>(Wh, Wl, Xs + par*128*36, C, m0, n0, lane);
        __syncthreads();
        #pragma unroll
        for (int i = 0; i < 3; i++)
            #pragma unroll
            for (int j = 0; j < 2; j++) {
                int pc = n0 + j*8 + 2*(lane & 3);
                int rr = m0 + i*16 + (lane >> 2);
                Ss[pc*196 + rr]           = C[i][j][0];
                Ss[(pc + 1)*196 + rr]     = C[i][j][1];
                Ss[pc*196 + rr + 8]       = C[i][j][2];
                Ss[(pc + 1)*196 + rr + 8] = C[i][j][3];
            }
        __syncthreads();
        int p0 = tile*32;
        #pragma unroll
        for (int c = 0; c < 2; c++) {
            int idx = t + 256*c;
            int p = idx >> 4, f4 = idx & 15;
            float4 v = *(const float4*)(Ss + p*196 + f4*4);
            u32 h0 = cvt2(v.y, v.x), h1 = cvt2(v.w, v.z);
            *(uint2*)(g_k16 + (size_t)(p0 + p)*64 + f4*4) = make_uint2(h0, h1);
        }
        #pragma unroll
        for (int c = 0; c < 4; c++) {
            int idx = t + 256*c;
            int p = idx >> 5, f5 = idx & 31;
            float4 v = *(const float4*)(Ss + p*196 + 64 + f5*4);
            u32 h0 = cvt2(v.y, v.x), h1 = cvt2(v.w, v.z);
            *(uint2*)(g_v16 + (size_t)(p0 + p)*128 + f5*4) = make_uint2(h0, h1);
        }
        __syncthreads();
        par ^= 1;
    }
}

// K2: merged q + partial: [Wc(128); Wq(64)] @ h_init. M=192, K=128, BN=64.
#define QP_SMEM (192*136*2*2 + 2*128*68*4 + 64*68*4)
__global__ void __launch_bounds__(256) k_qp(const float* __restrict__ hi,
        const float* __restrict__ Wq, const float* __restrict__ bq) {
    extern __shared__ char smraw[];
    __half* Wh = (__half*)smraw;
    __half* Wl = Wh + 192*136;
    float* Xs = (float*)(smraw + 192*136*2*2);
    float* Ss = Xs + 2*128*68;
    int t = threadIdx.x;

    for (int idx = t; idx < 192*128; idx += 256) {
        int m = idx >> 7, k = idx & 127;
        float w = (m < 128) ? g_Wc[m*128 + k] : Wq[(m - 128)*128 + k];
        w_split(w, Wh, Wl, m*136 + k);
    }
    const int NT = NPIXF/64;
    auto load_tile = [&](int buf, int tile) {
        float* X = Xs + buf*128*68;
        int p0 = tile*64, bb = p0 >> 17, s0 = p0 & (HWF - 1);
        const float* hb = hi + (size_t)bb*128*HWF + s0;
        #pragma unroll
        for (int c8 = 0; c8 < 8; c8++) {
            int chunk = t + 256*c8;
            int r = chunk >> 4, q = chunk & 15;
            cpa16(X + r*68 + q*4, hb + (size_t)r*HWF + q*4);
        }
    };
    int lane = t & 31, warp = t >> 5;
    int wm = warp >> 1, wn = warp & 1;
    int m0 = wm*48, n0 = wn*32;
    int r0 = m0 + (lane >> 2);

    int tile = blockIdx.x, par = 0;
    if (tile < NT) load_tile(0, tile);
    CPA_COMMIT();
    __syncthreads();
    for (; tile < NT; tile += GRD) {
        int nxt = tile + GRD;
        if (nxt < NT) load_tile(par ^ 1, nxt);
        CPA_COMMIT();
        CPA_WAIT1();
        __syncthreads();

        float C[3][4][4];
        #pragma unroll
        for (int i = 0; i < 3; i++) {
            int ra = r0 + i*16, rb = ra + 8;
            float b0 = (ra < 128) ? g_beff[ra] : bq[ra - 128];
            float b1 = (rb < 128) ? g_beff[rb] : bq[rb - 128];
            #pragma unroll
            for (int j = 0; j < 4; j++) {
                C[i][j][0] = C[i][j][1] = b0;
                C[i][j][2] = C[i][j][3] = b1;
            }
        }
        gemm_ms<3,4,128,68,136>(Wh, Wl, Xs + par*128*68, C, m0, n0, lane);

        int p0 = tile*64, bb = p0 >> 17, s0 = p0 & (HWF - 1);
        __half* pb = g_p16 + (size_t)bb*128*HWF + s0;
        #pragma unroll
        for (int i = 0; i < 3; i++) {
            int row16 = m0 + i*16;
            int rr = row16 + (lane >> 2);
            int pcb = n0 + 2*(lane & 3);
            if (row16 < 128) {
                #pragma unroll
                for (int j = 0; j < 4; j++) {
                    int pc = pcb + j*8;
                    *(u32*)(pb + (size_t)rr*HWF + pc)       = cvt2(C[i][j][1], C[i][j][0]);
                    *(u32*)(pb + (size_t)(rr + 8)*HWF + pc) = cvt2(C[i][j][3], C[i][j][2]);
                }
            } else {
                int rq = rr - 128;
                #pragma unroll
                for (int j = 0; j < 4; j++) {
                    int pc = pcb + j*8;
                    Ss[pc*68 + rq]           = C[i][j][0];
                    Ss[(pc + 1)*68 + rq]     = C[i][j][1];
                    Ss[pc*68 + rq + 8]       = C[i][j][2];
                    Ss[(pc + 1)*68 + rq + 8] = C[i][j][3];
                }
            }
        }
        __syncthreads();
        #pragma unroll
        for (int c = 0; c < 4; c++) {
            int idx = t + 256*c;
            int p = idx >> 4, f4 = idx & 15;
            float4 v = *(const float4*)(Ss + p*68 + f4*4);
            u32 h0 = cvt2(v.y, v.x), h1 = cvt2(v.w, v.z);
            *(uint2*)(g_q16 + (size_t)(p0 + p)*64 + f4*4) = make_uint2(h0, h1);
        }
        __syncthreads();
        par ^= 1;
    }
}

// K3: attention. fp16 k/v smem, min 3 blocks/SM.
#define ATTN_SMEM (NH*KPH*2 + NH*VPH*2 + 256*AP*4)
__global__ void __launch_bounds__(256, 3) k_attn() {
    extern __shared__ char smraw[];
    __half* ks = (__half*)smraw;
    __half* vs = ks + NH*KPH;
    float* as = (float*)(smraw + NH*KPH*2 + NH*VPH*2);
    int t = threadIdx.x;
    int b = blockIdx.z;
    int cy0 = blockIdx.y * CTY, cx0 = blockIdx.x * CTX;
    int fy0 = cy0*2, fx0 = cx0*2;

    for (int idx = t; idx < NH*8; idx += 256) {
        int pix = idx >> 3, c8 = idx & 7;
        int hy = pix / HX, hx = pix % HX;
        int gy = cy0 + hy - 1, gx = cx0 + hx - 1;
        uint4 v = make_uint4(0u, 0u, 0u, 0u);
        if ((unsigned)gy < CH2 && (unsigned)gx < CW2)
            v = *(const uint4*)(g_k16 + ((size_t)(b*HW2 + gy*CW2 + gx))*CCK + c8*8);
        *(uint4*)(ks + pix*KPH + c8*8) = v;
    }
    for (int idx = t; idx < NH*16; idx += 256) {
        int pix = idx >> 4, c8 = idx & 15;
        int hy = pix / HX, hx = pix % HX;
        int gy = cy0 + hy - 1, gx = cx0 + hx - 1;
        uint4 v = make_uint4(0u, 0u, 0u, 0u);
        if ((unsigned)gy < CH2 && (unsigned)gx < CW2)
            v = *(const uint4*)(g_v16 + ((size_t)(b*HW2 + gy*CW2 + gx))*CC + c8*8);
        *(uint4*)(vs + pix*VPH + c8*8) = v;
    }
    __syncthreads();

    {   // Phase A
        int p = t;
        int fy = p >> 5, fx = p & 31;
        int cy = fy >> 1, cx = fx >> 1;
        const uint4* gq = reinterpret_cast<const uint4*>(
            g_q16 + ((size_t)((b*CH + fy0 + fy)*CW + fx0 + fx))*CCK);
        const __half* kb = ks + (cy*HX + cx)*KPH;
        ull sc2[9];
        #pragma unroll
        for (int j = 0; j < 9; j++) sc2[j] = 0ull;
        #pragma unroll 2
        for (int cc = 0; cc < 8; cc++) {
            uint4 qv = gq[cc];
            float2 f0 = __half22float2(*reinterpret_cast<__half2*>(&qv.x));
            float2 f1 = __half22float2(*reinterpret_cast<__half2*>(&qv.y));
            float2 f2 = __half22float2(*reinterpret_cast<__half2*>(&qv.z));
            float2 f3 = __half22float2(*reinterpret_cast<__half2*>(&qv.w));
            ull q0 = pk2p(f0.x, f0.y), q1 = pk2p(f1.x, f1.y);
            ull q2 = pk2p(f2.x, f2.y), q3 = pk2p(f3.x, f3.y);
            int c = cc*8;
            #pragma unroll
            for (int dy = 0; dy < 3; dy++)
                #pragma unroll
                for (int dx = 0; dx < 3; dx++) {
                    int j = dy*3 + dx;
                    uint4 kv4 = *(const uint4*)(kb + (dy*HX + dx)*KPH + c);
                    float2 g0 = __half22float2(*reinterpret_cast<__half2*>(&kv4.x));
                    float2 g1 = __half22float2(*reinterpret_cast<__half2*>(&kv4.y));
                    float2 g2 = __half22float2(*reinterpret_cast<__half2*>(&kv4.z));
                    float2 g3 = __half22float2(*reinterpret_cast<__half2*>(&kv4.w));
                    sc2[j] = fma2(q0, pk2p(g0.x, g0.y), sc2[j]);
                    sc2[j] = fma2(q1, pk2p(g1.x, g1.y), sc2[j]);
                    sc2[j] = fma2(q2, pk2p(g2.x, g2.y), sc2[j]);
                    sc2[j] = fma2(q3, pk2p(g3.x, g3.y), sc2[j]);
                }
        }
        float sc[9];
        #pragma unroll
        for (int j = 0; j < 9; j++) { float2 v = upk(sc2[j]); sc[j] = v.x + v.y; }
        float m = sc[0];
        #pragma unroll
        for (int j = 1; j < 9; j++) m = fmaxf(m, sc[j]);
        float s = 0.f;
        #pragma unroll
        for (int j = 0; j < 9; j++) { sc[j] = __expf(sc[j] - m); s += sc[j]; }
        float inv = 1.f / s;
        #pragma unroll
        for (int j = 0; j < 9; j++) as[p*AP + j] = sc[j]*inv;
    }
    __syncthreads();

    {   // Phase B: fp16 v loads (uint2 = 4 ch)
        int cell = t & 63, cg = t >> 6;
        int cyl = cell >> 4, cxl = cell & 15;
        ull a01[9], a23[9];
        int p00 = (2*cyl)*32 + 2*cxl;
        int p10 = p00 + 32;
        #pragma unroll
        for (int j = 0; j < 9; j++) {
            a01[j] = pk2p(as[p00*AP + j], as[(p00 + 1)*AP + j]);
            a23[j] = pk2p(as[p10*AP + j], as[(p10 + 1)*AP + j]);
        }
        const __half* vb = vs + (cyl*HX + cxl)*VPH + cg*32;
        size_t obase = ((size_t)(b*CC + cg*32))*HWF
                     + (size_t)(fy0 + 2*cyl)*CW + fx0 + 2*cxl;
        #pragma unroll 2
        for (int c4 = 0; c4 < 8; c4++) {
            ull o01[4] = {0ull, 0ull, 0ull, 0ull};
            ull o23[4] = {0ull, 0ull, 0ull, 0ull};
            #pragma unroll
            for (int dy = 0; dy < 3; dy++)
                #pragma unroll
                for (int dx = 0; dx < 3; dx++) {
                    int j = dy*3 + dx;
                    uint2 vv2 = *(const uint2*)(vb + (dy*HX + dx)*VPH + c4*4);
                    float2 g0 = __half22float2(*reinterpret_cast<__half2*>(&vv2.x));
                    float2 g1 = __half22float2(*reinterpret_cast<__half2*>(&vv2.y));
                    o01[0] = fma2(a01[j], pk2(g0.x), o01[0]);
                    o01[1] = fma2(a01[j], pk2(g0.y), o01[1]);
                    o01[2] = fma2(a01[j], pk2(g1.x), o01[2]);
                    o01[3] = fma2(a01[j], pk2(g1.y), o01[3]);
                    o23[0] = fma2(a23[j], pk2(g0.x), o23[0]);
                    o23[1] = fma2(a23[j], pk2(g0.y), o23[1]);
                    o23[2] = fma2(a23[j], pk2(g1.x), o23[2]);
                    o23[3] = fma2(a23[j], pk2(g1.y), o23[3]);
                }
            #pragma unroll
            for (int e = 0; e < 4; e++) {
                float2 r01 = upk(o01[e]), r23 = upk(o23[e]);
                size_t oa = obase + (size_t)(c4*4 + e)*HWF;
                *reinterpret_cast<u32*>(g_x16 + oa)      = cvt2(r01.y, r01.x);
                *reinterpret_cast<u32*>(g_x16 + oa + CW) = cvt2(r23.y, r23.x);
            }
        }
    }
}

// K4: out = p + Wout@x. M=128, K=128, BN=128. fp16 staging, MF=2 NF=8.
#define XOP 136
#define O_SMEM (128*136*2*2 + 4*128*XOP*2)
__global__ void __launch_bounds__(256) k_out(const float* __restrict__ Wout,
        float* __restrict__ out) {
    extern __shared__ char smraw[];
    __half* Wh = (__half*)smraw;
    __half* Wl = Wh + 128*136;
    __half* Xp = (__half*)(smraw + 128*136*2*2);            // 2 x [128][136]
    __half* Xx = Xp + 2*128*XOP;                            // 2 x [128][136]
    int t = threadIdx.x;

    for (int idx = t; idx < 128*128; idx += 256) {
        int m = idx >> 7, k = idx & 127;
        w_split(Wout[idx], Wh, Wl, m*136 + k);
    }
    const int NT = NPIXF/128;
    auto load_tile = [&](int buf, int tile) {
        __half* XP = Xp + buf*128*XOP;
        __half* XX = Xx + buf*128*XOP;
        int p0 = tile*128, bb = p0 >> 17, s0 = p0 & (HWF - 1);
        const __half* pb = g_p16 + (size_t)bb*128*HWF + s0;
        const __half* xb = g_x16 + (size_t)bb*128*HWF + s0;
        #pragma unroll
        for (int c8 = 0; c8 < 8; c8++) {
            int chunk = t + 256*c8;
            int r = chunk >> 4, q = chunk & 15;
            cpa16(XP + r*XOP + q*8, pb + (size_t)r*HWF + q*8);
        }
        #pragma unroll
        for (int c8 = 0; c8 < 8; c8++) {
            int chunk = t + 256*c8;
            int r = chunk >> 4, q = chunk & 15;
            cpa16(XX + r*XOP + q*8, xb + (size_t)r*HWF + q*8);
        }
    };
    int lane = t & 31, warp = t >> 5;
    int wm = warp >> 1, wn = warp & 1;
    int m0 = wm*32, n0 = wn*64;
    int r0 = m0 + (lane >> 2);
    int pcb = n0 + 2*(lane & 3);

    int tile = blockIdx.x, par = 0;
    if (tile < NT) load_tile(0, tile);
    CPA_COMMIT();
    __syncthreads();
    for (; tile < NT; tile += GRD) {
        int nxt = tile + GRD;
        if (nxt < NT) load_tile(par ^ 1, nxt);
        CPA_COMMIT();
        CPA_WAIT1();
        __syncthreads();

        const __half* P = Xp + par*128*XOP;
        float C[2][8][4];
        #pragma unroll
        for (int i = 0; i < 2; i++) {
            int r = r0 + i*16;
            #pragma unroll
            for (int j = 0; j < 8; j++) {
                int pc = pcb + j*8;
                C[i][j][0] = __half2float(P[r*XOP + pc]);
                C[i][j][1] = __half2float(P[r*XOP + pc + 1]);
                C[i][j][2] = __half2float(P[(r + 8)*XOP + pc]);
                C[i][j][3] = __half2float(P[(r + 8)*XOP + pc + 1]);
            }
        }
        gemm_ms16<2,8,128,XOP,136>(Wh, Wl, Xx + par*128*XOP, C, m0, n0, lane);

        int p0 = tile*128, bb = p0 >> 17, s0 = p0 & (HWF - 1);
        float* ob = out + (size_t)bb*128*HWF + s0;
        #pragma unroll
        for (int i = 0; i < 2; i++) {
            int r = r0 + i*16;
            #pragma unroll
            for (int j = 0; j < 8; j++) {
                int ccol = pcb + j*8;
                *(float2*)(ob + (size_t)r*HWF + ccol)       = make_float2(C[i][j][0], C[i][j][1]);
                *(float2*)(ob + (size_t)(r + 8)*HWF + ccol) = make_float2(C[i][j][2], C[i][j][3]);
            }
        }
        __syncthreads();
        par ^= 1;
    }
}

extern "C" void kernel_launch(void* const* d_in, const int* in_sizes, int n_in,
                              void* d_out, int out_size) {
    const float* h_prev = (const float*)d_in[0];
    const float* h_init = (const float*)d_in[1];
    const float* Wq   = (const float*)d_in[2];
    const float* bq   = (const float*)d_in[3];
    const float* Wk   = (const float*)d_in[4];
    const float* bk   = (const float*)d_in[5];
    const float* Wvp  = (const float*)d_in[6];
    const float* bvp  = (const float*)d_in[7];
    const float* Wvi  = (const float*)d_in[8];
    const float* bvi  = (const float*)d_in[9];
    const float* Wout = (const float*)d_in[10];
    const float* bout = (const float*)d_in[11];
    float* out = (float*)d_out;

    cudaFuncSetAttribute(k_kv,   cudaFuncAttributeMaxDynamicSharedMemorySize, KV_SMEM);
    cudaFuncSetAttribute(k_qp,   cudaFuncAttributeMaxDynamicSharedMemorySize, QP_SMEM);
    cudaFuncSetAttribute(k_attn, cudaFuncAttributeMaxDynamicSharedMemorySize, ATTN_SMEM);
    cudaFuncSetAttribute(k_out,  cudaFuncAttributeMaxDynamicSharedMemorySize, O_SMEM);

    k_fuse<<<CC, CC>>>(Wout, Wvi, bvi, bout);
    k_kv<<<GRD, 256, KV_SMEM>>>(h_prev, Wk, bk, Wvp, bvp);
    k_qp<<<GRD, 256, QP_SMEM>>>(h_init, Wq, bq);
    dim3 ag(CW2/CTX, CH2/CTY, CB);
    k_attn<<<ag, 256, ATTN_SMEM>>>();
    k_out<<<GRD, 256, O_SMEM>>>(Wout, out);
}